// round 6
// baseline (speedup 1.0000x reference)
#include <cuda_runtime.h>
#include <math.h>
#include <stdint.h>

#define N_NODES 200000
#define N_EVENTS 50000
#define MEMD 128
#define TWO_E (2 * N_EVENTS)

// ---------------- scratch (static device globals) ----------------------------
__device__ int      g_last_pos[N_NODES];
__device__ int      g_sel[TWO_E];
__device__ int      g_count;
__device__ float    g_mem_new[(size_t)N_NODES * MEMD];
__device__ float    g_lu_new[N_NODES];
__device__ float    g_G[(size_t)TWO_E * 512];
__device__ float    g_kv[(size_t)N_EVENTS * 256];
__device__ float    g_logit[N_EVENTS * 2];
__device__ float    g_aexp[N_EVENTS * 2];
__device__ unsigned g_mx[N_NODES * 2];
__device__ float    g_denom[N_NODES * 2];
__device__ float    g_z[(size_t)N_NODES * MEMD];
__device__ float    g_te[(size_t)TWO_E * 64];     // GRU time-enc per selected row
__device__ float    g_te2[(size_t)N_EVENTS * 64]; // edge time-enc

__device__ __forceinline__ unsigned enc_f(float x) {
    unsigned u = __float_as_uint(x);
    return (u & 0x80000000u) ? ~u : (u | 0x80000000u);
}
__device__ __forceinline__ float dec_f(unsigned u) {
    unsigned v = (u & 0x80000000u) ? (u & 0x7FFFFFFFu) : ~u;
    return __uint_as_float(v);
}
__device__ __forceinline__ float sigmoidf_(float x) { return 1.f / (1.f + expf(-x)); }

__device__ __forceinline__ uint32_t f2tf32(float x) {
    uint32_t y;
    asm("cvt.rna.tf32.f32 %0, %1;" : "=r"(y) : "f"(x));
    return y;
}
__device__ __forceinline__ void mma_tf32(float4& d, const uint32_t a[4], const uint32_t b[2]) {
    asm volatile(
        "mma.sync.aligned.m16n8k8.row.col.f32.tf32.tf32.f32 "
        "{%0,%1,%2,%3}, {%4,%5,%6,%7}, {%8,%9}, {%0,%1,%2,%3};\n"
        : "+f"(d.x), "+f"(d.y), "+f"(d.z), "+f"(d.w)
        : "r"(a[0]), "r"(a[1]), "r"(a[2]), "r"(a[3]), "r"(b[0]), "r"(b[1]));
}

// 128x128 block tile MMA step over one staged BK=16 slice.
// 8 warps: warp_m = warp&3 (32-row stripes), warp_n = warp>>2 (64-col stripes).
__device__ __forceinline__ void mma_block(
    const uint32_t (*__restrict__ As)[136], const uint32_t (*__restrict__ Bs)[136],
    float4 acc[2][8], int warp_m, int warp_n, int g_, int t_)
{
#pragma unroll
    for (int ks = 0; ks < 2; ks++) {
        const int kb = ks * 8;
        uint32_t a[2][4], b[8][2];
#pragma unroll
        for (int mt = 0; mt < 2; mt++) {
            int rb = warp_m * 32 + mt * 16 + g_;
            a[mt][0] = As[kb + t_][rb];
            a[mt][1] = As[kb + t_][rb + 8];
            a[mt][2] = As[kb + t_ + 4][rb];
            a[mt][3] = As[kb + t_ + 4][rb + 8];
        }
#pragma unroll
        for (int nt = 0; nt < 8; nt++) {
            int cb = warp_n * 64 + nt * 8 + g_;
            b[nt][0] = Bs[kb + t_][cb];
            b[nt][1] = Bs[kb + t_ + 4][cb];
        }
#pragma unroll
        for (int mt = 0; mt < 2; mt++)
#pragma unroll
            for (int nt = 0; nt < 8; nt++) mma_tf32(acc[mt][nt], a[mt], b[nt]);
    }
}

// ---------------- init / copy / last-pos / compact ---------------------------
__global__ void k_init() {
    int i = blockIdx.x * blockDim.x + threadIdx.x;
    if (i < N_NODES) g_last_pos[i] = -1;
    if (i < 2 * N_NODES) { g_mx[i] = 0u; g_denom[i] = 0.f; }
    if (i == 0) g_count = 0;
}

__global__ void k_copy(const float4* __restrict__ mem, const float* __restrict__ lu) {
    int i = blockIdx.x * blockDim.x + threadIdx.x;
    if (i < N_NODES * (MEMD / 4)) ((float4*)g_mem_new)[i] = mem[i];
    if (i < N_NODES) g_lu_new[i] = lu[i];
}

__global__ void k_lastpos(const int* __restrict__ src, const int* __restrict__ dst) {
    int j = blockIdx.x * blockDim.x + threadIdx.x;
    if (j >= TWO_E) return;
    int id = (j < N_EVENTS) ? src[j] : dst[j - N_EVENTS];
    atomicMax(&g_last_pos[id], j);
}

__global__ void k_compact(const int* __restrict__ src, const int* __restrict__ dst) {
    int j = blockIdx.x * blockDim.x + threadIdx.x;
    if (j >= TWO_E) return;
    int id = (j < N_EVENTS) ? src[j] : dst[j - N_EVENTS];
    if (g_last_pos[id] == j) {
        int p = atomicAdd(&g_count, 1);
        g_sel[p] = j;
    }
}

// ---------------- time-enc precompute ----------------------------------------
__global__ void k_te_gru(const float* __restrict__ last_update, const float* __restrict__ t,
                         const int* __restrict__ src, const int* __restrict__ dst,
                         const float* __restrict__ time_w, const float* __restrict__ time_b)
{
    int i = blockIdx.x * blockDim.x + threadIdx.x;
    int m = i >> 6, j = i & 63;
    if (m >= g_count) return;
    int sel = g_sel[m];
    int e  = (sel < N_EVENTS) ? sel : sel - N_EVENTS;
    int id = (sel < N_EVENTS) ? src[e] : dst[e];
    float dt = t[e] - last_update[id];
    g_te[(size_t)m * 64 + j] = cosf(fmaf(dt, time_w[j], time_b[j]));
}

__global__ void k_te_edge(const float* __restrict__ t, const int* __restrict__ src,
                          const float* __restrict__ time_w, const float* __restrict__ time_b)
{
    int i = blockIdx.x * blockDim.x + threadIdx.x;
    if (i >= N_EVENTS * 64) return;
    int e = i >> 6, j = i & 63;
    float rt = g_lu_new[src[e]] - t[e];
    g_te2[i] = cosf(fmaf(rt, time_w[j], time_b[j]));
}

// ---------------- GRU GEMM (BM=128, BN=128, grid.y = gate group) --------------
// A(K=512 virtual) = [mem_id(128) | mem_oth(128) | msg(64) | te(64) | mem_id(128)]
// grp 0(r),1(z): K=[0,512); grp 2(i_n): K=[0,384); grp 3(h_n): K=[384,512)
__global__ __launch_bounds__(256) void k_gru_gemm(
    const float* __restrict__ memory,
    const int* __restrict__ src, const int* __restrict__ dst,
    const float* __restrict__ msg,
    const float* __restrict__ Wih, const float* __restrict__ Whh)
{
    const int count = g_count;
    const int m0 = blockIdx.x * 128;
    if (m0 >= count) return;
    const int grp = blockIdx.y;
    const int k_lo = (grp == 3) ? 384 : 0;
    const int k_hi = (grp == 2) ? 384 : 512;
    const int tid = threadIdx.x;
    const int lane = tid & 31, warp = tid >> 5;
    const int warp_m = warp & 3, warp_n = warp >> 2;
    const int g_ = lane >> 2, t_ = lane & 3;

    __shared__ int      s_id[128], s_oth[128], s_e[128];
    __shared__ uint32_t As[16][136];
    __shared__ uint32_t Bs[16][136];

    if (tid < 128) {
        int mm = min(m0 + tid, count - 1);
        int j = g_sel[mm];
        int e  = (j < N_EVENTS) ? j : j - N_EVENTS;
        s_id[tid]  = (j < N_EVENTS) ? src[e] : dst[e];
        s_oth[tid] = (j < N_EVENTS) ? dst[e] : src[e];
        s_e[tid] = e;
    }
    __syncthreads();

    float4 acc[2][8];
#pragma unroll
    for (int i = 0; i < 2; i++)
#pragma unroll
        for (int j = 0; j < 8; j++) acc[i][j] = make_float4(0.f, 0.f, 0.f, 0.f);

    for (int k0 = k_lo; k0 < k_hi; k0 += 16) {
#pragma unroll
        for (int s = 0; s < 8; s++) {
            int idx = tid + s * 256;
            int kk = idx & 15, m = idx >> 4;
            int k = k0 + kk;
            float v;
            if (k < 128)       v = memory[(size_t)s_id[m] * 128 + k];
            else if (k < 256)  v = memory[(size_t)s_oth[m] * 128 + (k - 128)];
            else if (k < 320)  v = msg[(size_t)s_e[m] * 64 + (k - 256)];
            else if (k < 384)  v = g_te[(size_t)min(m0 + m, count - 1) * 64 + (k - 320)];
            else               v = memory[(size_t)s_id[m] * 128 + (k - 384)];
            As[kk][m] = f2tf32(v);
        }
#pragma unroll
        for (int s = 0; s < 8; s++) {
            int idx = tid + s * 256;
            int kk = idx & 15, n = idx >> 4;
            int k = k0 + kk;
            float v;
            if (grp < 2)       v = (k < 384) ? Wih[(size_t)(grp * 128 + n) * 384 + k]
                                             : Whh[(size_t)(grp * 128 + n) * 128 + (k - 384)];
            else if (grp == 2) v = Wih[(size_t)(256 + n) * 384 + k];
            else               v = Whh[(size_t)(256 + n) * 128 + (k - 384)];
            Bs[kk][n] = f2tf32(v);
        }
        __syncthreads();
        mma_block(As, Bs, acc, warp_m, warp_n, g_, t_);
        __syncthreads();
    }
#pragma unroll
    for (int mt = 0; mt < 2; mt++)
#pragma unroll
        for (int nt = 0; nt < 8; nt++) {
            int r0 = m0 + warp_m * 32 + mt * 16 + g_;
            int c  = grp * 128 + warp_n * 64 + nt * 8 + 2 * t_;
            if (r0 < count)
                *(float2*)&g_G[(size_t)r0 * 512 + c] = make_float2(acc[mt][nt].x, acc[mt][nt].y);
            if (r0 + 8 < count)
                *(float2*)&g_G[(size_t)(r0 + 8) * 512 + c] = make_float2(acc[mt][nt].z, acc[mt][nt].w);
        }
}

// ---------------- GRU gates + scatter -----------------------------------------
__global__ void k_gates(const float* __restrict__ memory, const float* __restrict__ last_update,
                        const float* __restrict__ t,
                        const int* __restrict__ src, const int* __restrict__ dst,
                        const float* __restrict__ bih, const float* __restrict__ bhh)
{
    int m = blockIdx.x;
    if (m >= g_count) return;
    int j = g_sel[m];
    int e  = (j < N_EVENTS) ? j : j - N_EVENTS;
    int id = (j < N_EVENTS) ? src[e] : dst[e];
    int d = threadIdx.x;  // 128
    const float* G = &g_G[(size_t)m * 512];
    float g0 = G[d], g1 = G[128 + d], g2 = G[256 + d], g3 = G[384 + d];
    float h = memory[(size_t)id * 128 + d];
    float r = sigmoidf_(g0 + bih[d] + bhh[d]);
    float z = sigmoidf_(g1 + bih[128 + d] + bhh[128 + d]);
    float n = tanhf(g2 + bih[256 + d] + r * (g3 + bhh[256 + d]));
    g_mem_new[(size_t)id * 128 + d] = (1.f - z) * n + z * h;
    if (d == 0) g_lu_new[id] = fmaxf(last_update[id], t[e]);
}

// ---------------- per-edge k,v GEMM: [E x 256], BN=128, grid.y in {0,1} -------
__global__ __launch_bounds__(256) void k_kv_gemm(
    const float* __restrict__ msg, const int* __restrict__ src,
    const float* __restrict__ Wk, const float* __restrict__ bk,
    const float* __restrict__ Wv, const float* __restrict__ bv,
    const float* __restrict__ We)
{
    const int m0 = blockIdx.x * 128;
    const int bn0 = blockIdx.y * 128;
    const int tid = threadIdx.x;
    const int lane = tid & 31, warp = tid >> 5;
    const int warp_m = warp & 3, warp_n = warp >> 2;
    const int g_ = lane >> 2, t_ = lane & 3;

    __shared__ int      s_src[128], s_ec[128];
    __shared__ uint32_t As[16][136];
    __shared__ uint32_t Bs[16][136];

    if (tid < 128) {
        int e = min(m0 + tid, N_EVENTS - 1);
        s_src[tid] = src[e]; s_ec[tid] = e;
    }
    __syncthreads();

    float4 acc[2][8];
#pragma unroll
    for (int i = 0; i < 2; i++)
#pragma unroll
        for (int j = 0; j < 8; j++) acc[i][j] = make_float4(0.f, 0.f, 0.f, 0.f);

    for (int k0 = 0; k0 < 256; k0 += 16) {
#pragma unroll
        for (int s = 0; s < 8; s++) {
            int idx = tid + s * 256;
            int kk = idx & 15, m = idx >> 4;
            int k = k0 + kk;
            float v;
            if (k < 128)      v = g_mem_new[(size_t)s_src[m] * 128 + k];
            else if (k < 192) v = g_te2[(size_t)s_ec[m] * 64 + (k - 128)];
            else              v = msg[(size_t)s_ec[m] * 64 + (k - 192)];
            As[kk][m] = f2tf32(v);
        }
#pragma unroll
        for (int s = 0; s < 8; s++) {
            int idx = tid + s * 256;
            int kk = idx & 15, n = idx >> 4;
            int k = k0 + kk;
            int o = bn0 + n;
            float v;
            if (o < 128) v = (k < 128) ? Wk[(size_t)o * 128 + k] : We[(size_t)o * 128 + (k - 128)];
            else { int o2 = o - 128;
                   v = (k < 128) ? Wv[(size_t)o2 * 128 + k] : We[(size_t)o2 * 128 + (k - 128)]; }
            Bs[kk][n] = f2tf32(v);
        }
        __syncthreads();
        mma_block(As, Bs, acc, warp_m, warp_n, g_, t_);
        __syncthreads();
    }
#pragma unroll
    for (int mt = 0; mt < 2; mt++)
#pragma unroll
        for (int nt = 0; nt < 8; nt++) {
            int r0 = m0 + warp_m * 32 + mt * 16 + g_;
            int c  = bn0 + warp_n * 64 + nt * 8 + 2 * t_;
            float b0 = (c < 128) ? bk[c] : bv[c - 128];
            float b1 = (c + 1 < 128) ? bk[c + 1] : bv[c + 1 - 128];
            if (r0 < N_EVENTS)
                *(float2*)&g_kv[(size_t)r0 * 256 + c] =
                    make_float2(acc[mt][nt].x + b0, acc[mt][nt].y + b1);
            if (r0 + 8 < N_EVENTS)
                *(float2*)&g_kv[(size_t)(r0 + 8) * 256 + c] =
                    make_float2(acc[mt][nt].z + b0, acc[mt][nt].w + b1);
        }
}

// ---------------- q GEMM + fused logit dot + segment max ----------------------
__global__ __launch_bounds__(256) void k_q_logit(
    const int* __restrict__ dst,
    const float* __restrict__ Wq, const float* __restrict__ bq)
{
    const int m0 = blockIdx.x * 128;
    const int tid = threadIdx.x;
    const int lane = tid & 31, warp = tid >> 5;
    const int warp_m = warp & 3, warp_n = warp >> 2;
    const int g_ = lane >> 2, t_ = lane & 3;

    __shared__ int      s_dst[128];
    __shared__ uint32_t As[16][136];
    __shared__ uint32_t Bs[16][136];
    __shared__ float    logit_s[256];   // [row][head]

    if (tid < 128) s_dst[tid] = dst[min(m0 + tid, N_EVENTS - 1)];
    logit_s[tid] = 0.f;
    __syncthreads();

    float4 acc[2][8];
#pragma unroll
    for (int i = 0; i < 2; i++)
#pragma unroll
        for (int j = 0; j < 8; j++) acc[i][j] = make_float4(0.f, 0.f, 0.f, 0.f);

    for (int k0 = 0; k0 < 128; k0 += 16) {
#pragma unroll
        for (int s = 0; s < 8; s++) {
            int idx = tid + s * 256;
            int kk = idx & 15, m = idx >> 4;
            As[kk][m] = f2tf32(g_mem_new[(size_t)s_dst[m] * 128 + k0 + kk]);
        }
#pragma unroll
        for (int s = 0; s < 8; s++) {
            int idx = tid + s * 256;
            int kk = idx & 15, n = idx >> 4;
            Bs[kk][n] = f2tf32(Wq[(size_t)n * 128 + k0 + kk]);
        }
        __syncthreads();
        mma_block(As, Bs, acc, warp_m, warp_n, g_, t_);
        __syncthreads();
    }
    // epilogue: logit_partial[row][head] = sum_c (q_c + bq_c) * kv[row][c]
    // warp_n == head (cols [0,64) head0, [64,128) head1)
    float p[4] = {0.f, 0.f, 0.f, 0.f};   // [mt][lo/hi8]
#pragma unroll
    for (int mt = 0; mt < 2; mt++) {
        int r0 = m0 + warp_m * 32 + mt * 16 + g_;
        int r0c = min(r0, N_EVENTS - 1);
        int r1c = min(r0 + 8, N_EVENTS - 1);
#pragma unroll
        for (int nt = 0; nt < 8; nt++) {
            int c = warp_n * 64 + nt * 8 + 2 * t_;
            float bq0 = bq[c], bq1 = bq[c + 1];
            p[mt * 2 + 0] += (acc[mt][nt].x + bq0) * g_kv[(size_t)r0c * 256 + c]
                           + (acc[mt][nt].y + bq1) * g_kv[(size_t)r0c * 256 + c + 1];
            p[mt * 2 + 1] += (acc[mt][nt].z + bq0) * g_kv[(size_t)r1c * 256 + c]
                           + (acc[mt][nt].w + bq1) * g_kv[(size_t)r1c * 256 + c + 1];
        }
    }
#pragma unroll
    for (int mt = 0; mt < 2; mt++) {
        int rl = warp_m * 32 + mt * 16 + g_;
        atomicAdd(&logit_s[rl * 2 + warp_n], p[mt * 2 + 0]);
        atomicAdd(&logit_s[(rl + 8) * 2 + warp_n], p[mt * 2 + 1]);
    }
    __syncthreads();
    {
        int rl = tid >> 1, h = tid & 1;
        int m = m0 + rl;
        if (m < N_EVENTS) {
            float lg = logit_s[tid] * 0.125f;
            g_logit[m * 2 + h] = lg;
            atomicMax(&g_mx[(size_t)s_dst[rl] * 2 + h], enc_f(lg));
        }
    }
}

// ---------------- exp + denom --------------------------------------------------
__global__ void k_expsum(const int* __restrict__ dst) {
    int i = blockIdx.x * blockDim.x + threadIdx.x;
    if (i >= N_EVENTS * 2) return;
    int e = i >> 1, h = i & 1;
    int dn = dst[e];
    float mxv = dec_f(g_mx[dn * 2 + h]);
    float a = expf(g_logit[i] - mxv);
    g_aexp[i] = a;
    atomicAdd(&g_denom[dn * 2 + h], a);
}

// ---------------- skip GEMM: z = mem_new @ Wskip^T + bskip (BN=128) -----------
__global__ __launch_bounds__(256) void k_skip_gemm(
    const float* __restrict__ Wskip, const float* __restrict__ bskip)
{
    const int m0 = blockIdx.x * 128;
    const int tid = threadIdx.x;
    const int lane = tid & 31, warp = tid >> 5;
    const int warp_m = warp & 3, warp_n = warp >> 2;
    const int g_ = lane >> 2, t_ = lane & 3;

    __shared__ uint32_t As[16][136];
    __shared__ uint32_t Bs[16][136];

    float4 acc[2][8];
#pragma unroll
    for (int i = 0; i < 2; i++)
#pragma unroll
        for (int j = 0; j < 8; j++) acc[i][j] = make_float4(0.f, 0.f, 0.f, 0.f);

    for (int k0 = 0; k0 < 128; k0 += 16) {
#pragma unroll
        for (int s = 0; s < 8; s++) {
            int idx = tid + s * 256;
            int kk = idx & 15, m = idx >> 4;
            int mg = min(m0 + m, N_NODES - 1);
            As[kk][m] = f2tf32(g_mem_new[(size_t)mg * 128 + k0 + kk]);
        }
#pragma unroll
        for (int s = 0; s < 8; s++) {
            int idx = tid + s * 256;
            int kk = idx & 15, n = idx >> 4;
            Bs[kk][n] = f2tf32(Wskip[(size_t)n * 128 + k0 + kk]);
        }
        __syncthreads();
        mma_block(As, Bs, acc, warp_m, warp_n, g_, t_);
        __syncthreads();
    }
#pragma unroll
    for (int mt = 0; mt < 2; mt++)
#pragma unroll
        for (int nt = 0; nt < 8; nt++) {
            int r0 = m0 + warp_m * 32 + mt * 16 + g_;
            int c  = warp_n * 64 + nt * 8 + 2 * t_;
            float b0 = bskip[c], b1 = bskip[c + 1];
            if (r0 < N_NODES)
                *(float2*)&g_z[(size_t)r0 * 128 + c] =
                    make_float2(acc[mt][nt].x + b0, acc[mt][nt].y + b1);
            if (r0 + 8 < N_NODES)
                *(float2*)&g_z[(size_t)(r0 + 8) * 128 + c] =
                    make_float2(acc[mt][nt].z + b0, acc[mt][nt].w + b1);
        }
}

// ---------------- scatter attention output into z ------------------------------
__global__ void k_scatter(const int* __restrict__ dst) {
    int e = blockIdx.x;
    int d = threadIdx.x;          // 128
    int dn = dst[e];
    int h = d >> 6;
    float attn = g_aexp[e * 2 + h] / g_denom[dn * 2 + h];
    atomicAdd(&g_z[(size_t)dn * 128 + d], attn * g_kv[(size_t)e * 256 + 128 + d]);
}

// ---------------- link predictor: 3xTF32 GEMM + fused relu/Wlf reduction -------
__global__ __launch_bounds__(256) void k_linkpred(
    const int* __restrict__ src, const int* __restrict__ dst,
    const float* __restrict__ Wls, const float* __restrict__ bls,
    const float* __restrict__ Wld, const float* __restrict__ bld,
    const float* __restrict__ Wlf, const float* __restrict__ blf,
    float* __restrict__ out)
{
    const int m0 = blockIdx.x * 128;
    const int tid = threadIdx.x;
    const int lane = tid & 31, warp = tid >> 5;
    const int warp_m = warp & 3, warp_n = warp >> 2;
    const int g_ = lane >> 2, t_ = lane & 3;

    __shared__ int      s_src[128], s_dst[128];
    __shared__ uint32_t Ah[16][136], Al[16][136];
    __shared__ uint32_t Bh[16][136], Bl[16][136];
    __shared__ float    out_s[128];

    if (tid < 128) {
        int e = min(m0 + tid, N_EVENTS - 1);
        s_src[tid] = src[e];
        s_dst[tid] = dst[e];
        out_s[tid] = 0.f;
    }
    __syncthreads();

    float4 acc[2][8];
#pragma unroll
    for (int i = 0; i < 2; i++)
#pragma unroll
        for (int j = 0; j < 8; j++) acc[i][j] = make_float4(0.f, 0.f, 0.f, 0.f);

    for (int k0 = 0; k0 < 256; k0 += 16) {
#pragma unroll
        for (int s = 0; s < 8; s++) {
            int idx = tid + s * 256;
            int kk = idx & 15, m = idx >> 4;
            int k = k0 + kk;
            float v = (k < 128) ? g_z[(size_t)s_src[m] * 128 + k]
                                : g_z[(size_t)s_dst[m] * 128 + (k - 128)];
            uint32_t h = f2tf32(v);
            Ah[kk][m] = h;
            Al[kk][m] = f2tf32(v - __uint_as_float(h));
        }
#pragma unroll
        for (int s = 0; s < 8; s++) {
            int idx = tid + s * 256;
            int kk = idx & 15, n = idx >> 4;
            int k = k0 + kk;
            float v = (k < 128) ? Wls[(size_t)n * 128 + k] : Wld[(size_t)n * 128 + (k - 128)];
            uint32_t h = f2tf32(v);
            Bh[kk][n] = h;
            Bl[kk][n] = f2tf32(v - __uint_as_float(h));
        }
        __syncthreads();
        mma_block(Ah, Bl, acc, warp_m, warp_n, g_, t_);
        mma_block(Al, Bh, acc, warp_m, warp_n, g_, t_);
        mma_block(Ah, Bh, acc, warp_m, warp_n, g_, t_);
        __syncthreads();
    }
    // epilogue: relu(acc + bls + bld) dot Wlf, reduce per row
    float p[4] = {0.f, 0.f, 0.f, 0.f};
#pragma unroll
    for (int mt = 0; mt < 2; mt++) {
#pragma unroll
        for (int nt = 0; nt < 8; nt++) {
            int c = warp_n * 64 + nt * 8 + 2 * t_;
            float bb0 = bls[c] + bld[c], bb1 = bls[c + 1] + bld[c + 1];
            float w0 = Wlf[c], w1 = Wlf[c + 1];
            p[mt * 2 + 0] += fmaxf(acc[mt][nt].x + bb0, 0.f) * w0
                           + fmaxf(acc[mt][nt].y + bb1, 0.f) * w1;
            p[mt * 2 + 1] += fmaxf(acc[mt][nt].z + bb0, 0.f) * w0
                           + fmaxf(acc[mt][nt].w + bb1, 0.f) * w1;
        }
    }
#pragma unroll
    for (int mt = 0; mt < 2; mt++) {
        int rl = warp_m * 32 + mt * 16 + g_;
        atomicAdd(&out_s[rl], p[mt * 2 + 0]);
        atomicAdd(&out_s[rl + 8], p[mt * 2 + 1]);
    }
    __syncthreads();
    if (tid < 128 && m0 + tid < N_EVENTS)
        out[m0 + tid] = out_s[tid] + blf[0];
}

// ---------------- launch --------------------------------------------------------
extern "C" void kernel_launch(void* const* d_in, const int* in_sizes, int n_in,
                              void* d_out, int out_size)
{
    const float* memory      = (const float*)d_in[0];
    const float* last_update = (const float*)d_in[1];
    const float* t           = (const float*)d_in[2];
    const float* msg         = (const float*)d_in[3];
    const int*   src         = (const int*)d_in[4];
    const int*   dst         = (const int*)d_in[5];
    const float* time_w      = (const float*)d_in[6];
    const float* time_b      = (const float*)d_in[7];
    const float* gru_Wih     = (const float*)d_in[8];
    const float* gru_bih     = (const float*)d_in[9];
    const float* gru_Whh     = (const float*)d_in[10];
    const float* gru_bhh     = (const float*)d_in[11];
    const float* Wq          = (const float*)d_in[12];
    const float* bq          = (const float*)d_in[13];
    const float* Wk          = (const float*)d_in[14];
    const float* bk          = (const float*)d_in[15];
    const float* Wv          = (const float*)d_in[16];
    const float* bv          = (const float*)d_in[17];
    const float* We          = (const float*)d_in[18];
    const float* Wskip       = (const float*)d_in[19];
    const float* bskip       = (const float*)d_in[20];
    const float* Wls         = (const float*)d_in[21];
    const float* bls         = (const float*)d_in[22];
    const float* Wld         = (const float*)d_in[23];
    const float* bld         = (const float*)d_in[24];
    const float* Wlf         = (const float*)d_in[25];
    const float* blf         = (const float*)d_in[26];
    float* out = (float*)d_out;

    k_init<<<(2 * N_NODES + 255) / 256, 256>>>();
    k_copy<<<(N_NODES * (MEMD / 4) + 255) / 256, 256>>>((const float4*)memory, last_update);
    k_lastpos<<<(TWO_E + 255) / 256, 256>>>(src, dst);
    k_compact<<<(TWO_E + 255) / 256, 256>>>(src, dst);
    k_te_gru<<<(TWO_E * 64 + 255) / 256, 256>>>(last_update, t, src, dst, time_w, time_b);
    {
        dim3 grid((TWO_E + 127) / 128, 4);
        k_gru_gemm<<<grid, 256>>>(memory, src, dst, msg, gru_Wih, gru_Whh);
    }
    k_gates<<<TWO_E, 128>>>(memory, last_update, t, src, dst, gru_bih, gru_bhh);
    k_te_edge<<<(N_EVENTS * 64 + 255) / 256, 256>>>(t, src, time_w, time_b);
    {
        dim3 grid((N_EVENTS + 127) / 128, 2);
        k_kv_gemm<<<grid, 256>>>(msg, src, Wk, bk, Wv, bv, We);
    }
    k_q_logit<<<(N_EVENTS + 127) / 128, 256>>>(dst, Wq, bq);
    k_expsum<<<(N_EVENTS * 2 + 255) / 256, 256>>>(dst);
    k_skip_gemm<<<(N_NODES + 127) / 128, 256>>>(Wskip, bskip);
    k_scatter<<<N_EVENTS, 128>>>(dst);
    k_linkpred<<<(N_EVENTS + 127) / 128, 256>>>(src, dst, Wls, bls, Wld, bld, Wlf, blf, out);
}

// round 10
// speedup vs baseline: 1.0396x; 1.0396x over previous
#include <cuda_runtime.h>
#include <math.h>
#include <stdint.h>

#define N_NODES 200000
#define N_EVENTS 50000
#define TWO_E (2 * N_EVENTS)

__device__ int      g_last_pos[N_NODES];
__device__ int      g_sel[TWO_E];
__device__ int      g_count;
__device__ float    g_mem_new[(size_t)N_NODES * 128];
__device__ float    g_lu_new[N_NODES];
__device__ float    g_kv[(size_t)N_EVENTS * 256];
__device__ float    g_logit[N_EVENTS * 2];
__device__ float    g_aexp[N_EVENTS * 2];
__device__ unsigned g_mx[N_NODES * 2];
__device__ float    g_denom[N_NODES * 2];
__device__ float    g_z[(size_t)N_NODES * 128];
__device__ float    g_te[(size_t)TWO_E * 64];
__device__ float    g_te2[(size_t)N_EVENTS * 64];

__device__ __forceinline__ unsigned enc_f(float x) {
    unsigned u = __float_as_uint(x);
    return (u & 0x80000000u) ? ~u : (u | 0x80000000u);
}
__device__ __forceinline__ float dec_f(unsigned u) {
    unsigned v = (u & 0x80000000u) ? (u & 0x7FFFFFFFu) : ~u;
    return __uint_as_float(v);
}
__device__ __forceinline__ float sigmoidf_(float x) { return 1.f / (1.f + expf(-x)); }
__device__ __forceinline__ uint32_t f2tf32(float x) {
    uint32_t y; asm("cvt.rna.tf32.f32 %0, %1;" : "=r"(y) : "f"(x)); return y;
}
__device__ __forceinline__ uint32_t cvt_b(uint32_t b) {
    uint32_t y; asm("cvt.rna.tf32.f32 %0, %1;" : "=r"(y) : "f"(__uint_as_float(b))); return y;
}
__device__ __forceinline__ uint32_t smem_u32(const void* p) {
    uint32_t a;
    asm("{ .reg .u64 t; cvta.to.shared.u64 t, %1; cvt.u32.u64 %0, t; }" : "=r"(a) : "l"(p));
    return a;
}
__device__ __forceinline__ void cp4(uint32_t d, const void* s) {
    asm volatile("cp.async.ca.shared.global [%0], [%1], 4;"
                 :: "r"(d), "l"(__cvta_generic_to_global(s)) : "memory");
}
#define CPCOMMIT() asm volatile("cp.async.commit_group;" ::: "memory")
#define CPWAIT1()  asm volatile("cp.async.wait_group 1;" ::: "memory")
#define CPWAIT0()  asm volatile("cp.async.wait_group 0;" ::: "memory")

__device__ __forceinline__ void mma_tf32(float4& d, const uint32_t a[4], const uint32_t b[2]) {
    asm volatile(
        "mma.sync.aligned.m16n8k8.row.col.f32.tf32.tf32.f32 "
        "{%0,%1,%2,%3}, {%4,%5,%6,%7}, {%8,%9}, {%0,%1,%2,%3};\n"
        : "+f"(d.x), "+f"(d.y), "+f"(d.z), "+f"(d.w)
        : "r"(a[0]), "r"(a[1]), "r"(a[2]), "r"(a[3]), "r"(b[0]), "r"(b[1]));
}

// one BK=16 slice; A 128 rows (pitch 136), B NT*8*... cols (pitch BP). cvt at load.
template<int NT, int BP>
__device__ __forceinline__ void mma_blockT(const uint32_t* __restrict__ As,
                                           const uint32_t* __restrict__ Bs,
                                           float4 (*acc)[NT],
                                           int warp_m, int warp_n, int g_, int t_)
{
#pragma unroll
    for (int ks = 0; ks < 2; ks++) {
        const int kb = ks * 8;
        uint32_t a[2][4], b[NT][2];
#pragma unroll
        for (int mt = 0; mt < 2; mt++) {
            int rb = warp_m * 32 + mt * 16 + g_;
            a[mt][0] = cvt_b(As[(kb + t_) * 136 + rb]);
            a[mt][1] = cvt_b(As[(kb + t_) * 136 + rb + 8]);
            a[mt][2] = cvt_b(As[(kb + t_ + 4) * 136 + rb]);
            a[mt][3] = cvt_b(As[(kb + t_ + 4) * 136 + rb + 8]);
        }
#pragma unroll
        for (int nt = 0; nt < NT; nt++) {
            int cb = warp_n * (NT * 8) + nt * 8 + g_;
            b[nt][0] = cvt_b(Bs[(kb + t_) * BP + cb]);
            b[nt][1] = cvt_b(Bs[(kb + t_ + 4) * BP + cb]);
        }
#pragma unroll
        for (int mt = 0; mt < 2; mt++)
#pragma unroll
            for (int nt = 0; nt < NT; nt++) mma_tf32(acc[mt][nt], a[mt], b[nt]);
    }
}

// ---------------- small kernels ----------------------------------------------
__global__ void k_init() {
    int i = blockIdx.x * blockDim.x + threadIdx.x;
    if (i < N_NODES) g_last_pos[i] = -1;
    if (i < 2 * N_NODES) { g_mx[i] = 0u; g_denom[i] = 0.f; }
    if (i == 0) g_count = 0;
}
__global__ void k_lastpos(const int* __restrict__ src, const int* __restrict__ dst) {
    int j = blockIdx.x * blockDim.x + threadIdx.x;
    if (j >= TWO_E) return;
    int id = (j < N_EVENTS) ? src[j] : dst[j - N_EVENTS];
    atomicMax(&g_last_pos[id], j);
}
__global__ void k_compact(const int* __restrict__ src, const int* __restrict__ dst,
                          const float* __restrict__ lu, const float* __restrict__ t) {
    int j = blockIdx.x * blockDim.x + threadIdx.x;
    if (j >= TWO_E) return;
    int e = (j < N_EVENTS) ? j : j - N_EVENTS;
    int id = (j < N_EVENTS) ? src[e] : dst[e];
    if (g_last_pos[id] == j) {
        int p = atomicAdd(&g_count, 1);
        g_sel[p] = j;
        g_lu_new[id] = fmaxf(lu[id], t[e]);
    }
}
__global__ void k_te_gru(const float* __restrict__ last_update, const float* __restrict__ t,
                         const int* __restrict__ src, const int* __restrict__ dst,
                         const float* __restrict__ time_w, const float* __restrict__ time_b)
{
    int i = blockIdx.x * blockDim.x + threadIdx.x;
    int m = i >> 6, j = i & 63;
    if (m >= g_count) return;
    int sel = g_sel[m];
    int e  = (sel < N_EVENTS) ? sel : sel - N_EVENTS;
    int id = (sel < N_EVENTS) ? src[e] : dst[e];
    float dt = t[e] - last_update[id];
    g_te[(size_t)m * 64 + j] = cosf(fmaf(dt, time_w[j], time_b[j]));
}
__global__ void k_te_edge(const float* __restrict__ t, const int* __restrict__ src,
                          const float* __restrict__ time_w, const float* __restrict__ time_b)
{
    int i = blockIdx.x * blockDim.x + threadIdx.x;
    if (i >= N_EVENTS * 64) return;
    int e = i >> 6, j = i & 63;
    float rt = g_lu_new[src[e]] - t[e];
    g_te2[i] = cosf(fmaf(rt, time_w[j], time_b[j]));
}
__global__ void k_expsum(const int* __restrict__ dst) {
    int i = blockIdx.x * blockDim.x + threadIdx.x;
    if (i >= N_EVENTS * 2) return;
    int e = i >> 1, h = i & 1;
    int dn = dst[e];
    float a = expf(g_logit[i] - dec_f(g_mx[dn * 2 + h]));
    g_aexp[i] = a;
    atomicAdd(&g_denom[dn * 2 + h], a);
}
__global__ void k_scatter(const int* __restrict__ dst) {
    int e = blockIdx.x, d = threadIdx.x;
    int dn = dst[e], h = d >> 6;
    float attn = g_aexp[e * 2 + h] / g_denom[dn * 2 + h];
    atomicAdd(&g_z[(size_t)dn * 128 + d], attn * g_kv[(size_t)e * 256 + 128 + d]);
}

// ---------------- GRU: fused gates, grid=(rows/128, 4 col-quarters) -----------
// virtual A(K=512) = [mem_id|mem_oth|msg|te|mem_id]; tile list: grp0:32, grp1:32,
// grp2(K<384):24, grp3(K>=384):8 => 96 BK=16 tiles.
__global__ __launch_bounds__(256) void k_gru(
    const float* __restrict__ memory, const float* __restrict__ msg,
    const int* __restrict__ src, const int* __restrict__ dst,
    const float* __restrict__ Wih, const float* __restrict__ Whh,
    const float* __restrict__ bih, const float* __restrict__ bhh)
{
    const int count = g_count;
    const int m0 = blockIdx.x * 128;
    if (m0 >= count) return;
    const int q = blockIdx.y;
    const int tid = threadIdx.x, lane = tid & 31, wid = tid >> 5;
    const int warp_m = wid & 3, warp_n = wid >> 2, g_ = lane >> 2, t_ = lane & 3;

    __shared__ int s_id[128], s_oth[128], s_e[128];
    __shared__ uint32_t As[2][16][136];
    __shared__ uint32_t Bs[2][16][40];
    const uint32_t aB = smem_u32(&As[0][0][0]);
    const uint32_t bB = smem_u32(&Bs[0][0][0]);

    if (tid < 128) {
        int mm = min(m0 + tid, count - 1);
        int j = g_sel[mm];
        int e = (j < N_EVENTS) ? j : j - N_EVENTS;
        s_id[tid]  = (j < N_EVENTS) ? src[e] : dst[e];
        s_oth[tid] = (j < N_EVENTS) ? dst[e] : src[e];
        s_e[tid] = e;
    }
    __syncthreads();

    auto stage = [&](int i, int buf) {
        int grp, k0;
        if (i < 64)      { grp = i >> 5; k0 = (i & 31) * 16; }
        else if (i < 88) { grp = 2; k0 = (i - 64) * 16; }
        else             { grp = 3; k0 = 384 + (i - 88) * 16; }
#pragma unroll
        for (int s = 0; s < 8; s++) {
            int idx = tid + s * 256;
            int kk = idx & 15, m = idx >> 4;
            int k = k0 + kk;
            const float* p;
            if (k < 128)      p = &memory[(size_t)s_id[m] * 128 + k];
            else if (k < 256) p = &memory[(size_t)s_oth[m] * 128 + (k - 128)];
            else if (k < 320) p = &msg[(size_t)s_e[m] * 64 + (k - 256)];
            else if (k < 384) p = &g_te[(size_t)min(m0 + m, count - 1) * 64 + (k - 320)];
            else              p = &memory[(size_t)s_id[m] * 128 + (k - 384)];
            cp4(aB + (uint32_t)((buf * 16 + kk) * 136 + m) * 4, p);
        }
#pragma unroll
        for (int s = 0; s < 2; s++) {
            int idx = tid + s * 256;
            int kk = idx & 15, n = idx >> 4;
            int k = k0 + kk;
            int r = q * 32 + n;
            const float* p;
            if (grp < 2)       p = (k < 384) ? &Wih[(size_t)(grp * 128 + r) * 384 + k]
                                             : &Whh[(size_t)(grp * 128 + r) * 128 + (k - 384)];
            else if (grp == 2) p = &Wih[(size_t)(256 + r) * 384 + k];
            else               p = &Whh[(size_t)(256 + r) * 128 + (k - 384)];
            cp4(bB + (uint32_t)((buf * 16 + kk) * 40 + n) * 4, p);
        }
        CPCOMMIT();
    };

    float4 acc[4][2][2];
#pragma unroll
    for (int g = 0; g < 4; g++)
#pragma unroll
        for (int i = 0; i < 2; i++)
#pragma unroll
            for (int j = 0; j < 2; j++) acc[g][i][j] = make_float4(0.f, 0.f, 0.f, 0.f);

    stage(0, 0);
    for (int i = 0; i < 96; i++) {
        if (i + 1 < 96) { stage(i + 1, (i + 1) & 1); CPWAIT1(); } else { CPWAIT0(); }
        __syncthreads();
        int grp = (i < 64) ? (i >> 5) : (i < 88 ? 2 : 3);
        mma_blockT<2, 40>(&As[i & 1][0][0], &Bs[i & 1][0][0], acc[grp], warp_m, warp_n, g_, t_);
        __syncthreads();
    }

    // fused gates epilogue
#pragma unroll
    for (int mt = 0; mt < 2; mt++)
#pragma unroll
    for (int nt = 0; nt < 2; nt++) {
        int cl = warp_n * 16 + nt * 8 + 2 * t_;
        int d = q * 32 + cl;
        float br0 = bih[d] + bhh[d],             br1 = bih[d + 1] + bhh[d + 1];
        float bz0 = bih[128 + d] + bhh[128 + d], bz1 = bih[129 + d] + bhh[129 + d];
        float bi0 = bih[256 + d],                bi1 = bih[257 + d];
        float bn0 = bhh[256 + d],                bn1 = bhh[257 + d];
#pragma unroll
        for (int hf = 0; hf < 2; hf++) {
            int rl = warp_m * 32 + mt * 16 + g_ + hf * 8;
            int m = m0 + rl;
            if (m < count) {
                int id = s_id[rl];
                float2 h = *(const float2*)&memory[(size_t)id * 128 + d];
                float R0, R1, Z0, Z1, I0, I1, H0, H1;
                if (hf == 0) {
                    R0 = acc[0][mt][nt].x; R1 = acc[0][mt][nt].y;
                    Z0 = acc[1][mt][nt].x; Z1 = acc[1][mt][nt].y;
                    I0 = acc[2][mt][nt].x; I1 = acc[2][mt][nt].y;
                    H0 = acc[3][mt][nt].x; H1 = acc[3][mt][nt].y;
                } else {
                    R0 = acc[0][mt][nt].z; R1 = acc[0][mt][nt].w;
                    Z0 = acc[1][mt][nt].z; Z1 = acc[1][mt][nt].w;
                    I0 = acc[2][mt][nt].z; I1 = acc[2][mt][nt].w;
                    H0 = acc[3][mt][nt].z; H1 = acc[3][mt][nt].w;
                }
                float r0 = sigmoidf_(R0 + br0), z0 = sigmoidf_(Z0 + bz0);
                float n0 = tanhf(I0 + bi0 + r0 * (H0 + bn0));
                float r1 = sigmoidf_(R1 + br1), z1 = sigmoidf_(Z1 + bz1);
                float n1 = tanhf(I1 + bi1 + r1 * (H1 + bn1));
                float2 o;
                o.x = (1.f - z0) * n0 + z0 * h.x;
                o.y = (1.f - z1) * n1 + z1 * h.y;
                *(float2*)&g_mem_new[(size_t)id * 128 + d] = o;
            }
        }
    }
}

// ---------------- kv GEMM: [E x 256], pipelined, grid=(E/128, 2) --------------
__global__ __launch_bounds__(256) void k_kv(
    const float* __restrict__ msg, const int* __restrict__ src,
    const float* __restrict__ Wk, const float* __restrict__ bk,
    const float* __restrict__ Wv, const float* __restrict__ bv,
    const float* __restrict__ We)
{
    const int m0 = blockIdx.x * 128;
    const int bn0 = blockIdx.y * 128;
    const int tid = threadIdx.x, lane = tid & 31, wid = tid >> 5;
    const int warp_m = wid & 3, warp_n = wid >> 2, g_ = lane >> 2, t_ = lane & 3;

    __shared__ int s_src[128], s_ec[128];
    __shared__ uint32_t As[2][16][136];
    __shared__ uint32_t Bs[2][16][136];
    const uint32_t aB = smem_u32(&As[0][0][0]);
    const uint32_t bB = smem_u32(&Bs[0][0][0]);

    if (tid < 128) {
        int e = min(m0 + tid, N_EVENTS - 1);
        s_src[tid] = src[e]; s_ec[tid] = e;
    }
    __syncthreads();

    auto stage = [&](int tile, int buf) {
        int k0 = tile * 16;
#pragma unroll
        for (int s = 0; s < 8; s++) {
            int idx = tid + s * 256;
            int kk = idx & 15, m = idx >> 4;
            int k = k0 + kk;
            const float* p;
            if (k < 128)      p = &g_mem_new[(size_t)s_src[m] * 128 + k];
            else if (k < 192) p = &g_te2[(size_t)s_ec[m] * 64 + (k - 128)];
            else              p = &msg[(size_t)s_ec[m] * 64 + (k - 192)];
            cp4(aB + (uint32_t)((buf * 16 + kk) * 136 + m) * 4, p);
        }
#pragma unroll
        for (int s = 0; s < 8; s++) {
            int idx = tid + s * 256;
            int kk = idx & 15, n = idx >> 4;
            int k = k0 + kk;
            int o = bn0 + n;
            const float* p;
            if (o < 128) p = (k < 128) ? &Wk[(size_t)o * 128 + k] : &We[(size_t)o * 128 + (k - 128)];
            else { int o2 = o - 128;
                   p = (k < 128) ? &Wv[(size_t)o2 * 128 + k] : &We[(size_t)o2 * 128 + (k - 128)]; }
            cp4(bB + (uint32_t)((buf * 16 + kk) * 136 + n) * 4, p);
        }
        CPCOMMIT();
    };

    float4 acc[2][8];
#pragma unroll
    for (int i = 0; i < 2; i++)
#pragma unroll
        for (int j = 0; j < 8; j++) acc[i][j] = make_float4(0.f, 0.f, 0.f, 0.f);

    stage(0, 0);
    for (int i = 0; i < 16; i++) {
        if (i + 1 < 16) { stage(i + 1, (i + 1) & 1); CPWAIT1(); } else { CPWAIT0(); }
        __syncthreads();
        mma_blockT<8, 136>(&As[i & 1][0][0], &Bs[i & 1][0][0], acc, warp_m, warp_n, g_, t_);
        __syncthreads();
    }
#pragma unroll
    for (int mt = 0; mt < 2; mt++)
#pragma unroll
        for (int nt = 0; nt < 8; nt++) {
            int r0 = m0 + warp_m * 32 + mt * 16 + g_;
            int c  = bn0 + warp_n * 64 + nt * 8 + 2 * t_;
            float b0 = (c < 128) ? bk[c] : bv[c - 128];
            float b1 = (c + 1 < 128) ? bk[c + 1] : bv[c + 1 - 128];
            if (r0 < N_EVENTS)
                *(float2*)&g_kv[(size_t)r0 * 256 + c] =
                    make_float2(acc[mt][nt].x + b0, acc[mt][nt].y + b1);
            if (r0 + 8 < N_EVENTS)
                *(float2*)&g_kv[(size_t)(r0 + 8) * 256 + c] =
                    make_float2(acc[mt][nt].z + b0, acc[mt][nt].w + b1);
        }
}

// ---------------- q GEMM + fused logit + segment max, pipelined ---------------
__global__ __launch_bounds__(256) void k_q(
    const int* __restrict__ dst,
    const float* __restrict__ Wq, const float* __restrict__ bq)
{
    const int m0 = blockIdx.x * 128;
    const int tid = threadIdx.x, lane = tid & 31, wid = tid >> 5;
    const int warp_m = wid & 3, warp_n = wid >> 2, g_ = lane >> 2, t_ = lane & 3;

    __shared__ int s_dst[128];
    __shared__ uint32_t As[2][16][136];
    __shared__ uint32_t Bs[2][16][136];
    __shared__ float logit_s[256];
    const uint32_t aB = smem_u32(&As[0][0][0]);
    const uint32_t bB = smem_u32(&Bs[0][0][0]);

    if (tid < 128) s_dst[tid] = dst[min(m0 + tid, N_EVENTS - 1)];
    logit_s[tid] = 0.f;
    __syncthreads();

    auto stage = [&](int tile, int buf) {
        int k0 = tile * 16;
#pragma unroll
        for (int s = 0; s < 8; s++) {
            int idx = tid + s * 256;
            int kk = idx & 15, m = idx >> 4;
            cp4(aB + (uint32_t)((buf * 16 + kk) * 136 + m) * 4,
                &g_mem_new[(size_t)s_dst[m] * 128 + k0 + kk]);
        }
#pragma unroll
        for (int s = 0; s < 8; s++) {
            int idx = tid + s * 256;
            int kk = idx & 15, n = idx >> 4;
            cp4(bB + (uint32_t)((buf * 16 + kk) * 136 + n) * 4,
                &Wq[(size_t)n * 128 + k0 + kk]);
        }
        CPCOMMIT();
    };

    float4 acc[2][8];
#pragma unroll
    for (int i = 0; i < 2; i++)
#pragma unroll
        for (int j = 0; j < 8; j++) acc[i][j] = make_float4(0.f, 0.f, 0.f, 0.f);

    stage(0, 0);
    for (int i = 0; i < 8; i++) {
        if (i + 1 < 8) { stage(i + 1, (i + 1) & 1); CPWAIT1(); } else { CPWAIT0(); }
        __syncthreads();
        mma_blockT<8, 136>(&As[i & 1][0][0], &Bs[i & 1][0][0], acc, warp_m, warp_n, g_, t_);
        __syncthreads();
    }
    // logit epilogue: head = warp_n (cols [0,64)=h0, [64,128)=h1)
    float p[4] = {0.f, 0.f, 0.f, 0.f};
#pragma unroll
    for (int mt = 0; mt < 2; mt++) {
        int r0 = m0 + warp_m * 32 + mt * 16 + g_;
        int r0c = min(r0, N_EVENTS - 1);
        int r1c = min(r0 + 8, N_EVENTS - 1);
#pragma unroll
        for (int nt = 0; nt < 8; nt++) {
            int c = warp_n * 64 + nt * 8 + 2 * t_;
            float bq0 = bq[c], bq1 = bq[c + 1];
            p[mt * 2 + 0] += (acc[mt][nt].x + bq0) * g_kv[(size_t)r0c * 256 + c]
                           + (acc[mt][nt].y + bq1) * g_kv[(size_t)r0c * 256 + c + 1];
            p[mt * 2 + 1] += (acc[mt][nt].z + bq0) * g_kv[(size_t)r1c * 256 + c]
                           + (acc[mt][nt].w + bq1) * g_kv[(size_t)r1c * 256 + c + 1];
        }
    }
#pragma unroll
    for (int mt = 0; mt < 2; mt++) {
        int rl = warp_m * 32 + mt * 16 + g_;
        atomicAdd(&logit_s[rl * 2 + warp_n], p[mt * 2 + 0]);
        atomicAdd(&logit_s[(rl + 8) * 2 + warp_n], p[mt * 2 + 1]);
    }
    __syncthreads();
    {
        int rl = tid >> 1, h = tid & 1;
        int m = m0 + rl;
        if (m < N_EVENTS) {
            float lg = logit_s[tid] * 0.125f;
            g_logit[m * 2 + h] = lg;
            atomicMax(&g_mx[(size_t)s_dst[rl] * 2 + h], enc_f(lg));
        }
    }
}

// ---------------- skip GEMM over COMPACTED nodes only, pipelined --------------
__global__ __launch_bounds__(256) void k_skip(
    const int* __restrict__ src, const int* __restrict__ dst,
    const float* __restrict__ Wskip, const float* __restrict__ bskip)
{
    const int count = g_count;
    const int m0 = blockIdx.x * 128;
    if (m0 >= count) return;
    const int tid = threadIdx.x, lane = tid & 31, wid = tid >> 5;
    const int warp_m = wid & 3, warp_n = wid >> 2, g_ = lane >> 2, t_ = lane & 3;

    __shared__ int s_id[128];
    __shared__ uint32_t As[2][16][136];
    __shared__ uint32_t Bs[2][16][136];
    const uint32_t aB = smem_u32(&As[0][0][0]);
    const uint32_t bB = smem_u32(&Bs[0][0][0]);

    if (tid < 128) {
        int mm = min(m0 + tid, count - 1);
        int j = g_sel[mm];
        int e = (j < N_EVENTS) ? j : j - N_EVENTS;
        s_id[tid] = (j < N_EVENTS) ? src[e] : dst[e];
    }
    __syncthreads();

    auto stage = [&](int tile, int buf) {
        int k0 = tile * 16;
#pragma unroll
        for (int s = 0; s < 8; s++) {
            int idx = tid + s * 256;
            int kk = idx & 15, m = idx >> 4;
            cp4(aB + (uint32_t)((buf * 16 + kk) * 136 + m) * 4,
                &g_mem_new[(size_t)s_id[m] * 128 + k0 + kk]);
        }
#pragma unroll
        for (int s = 0; s < 8; s++) {
            int idx = tid + s * 256;
            int kk = idx & 15, n = idx >> 4;
            cp4(bB + (uint32_t)((buf * 16 + kk) * 136 + n) * 4,
                &Wskip[(size_t)n * 128 + k0 + kk]);
        }
        CPCOMMIT();
    };

    float4 acc[2][8];
#pragma unroll
    for (int i = 0; i < 2; i++)
#pragma unroll
        for (int j = 0; j < 8; j++) acc[i][j] = make_float4(0.f, 0.f, 0.f, 0.f);

    stage(0, 0);
    for (int i = 0; i < 8; i++) {
        if (i + 1 < 8) { stage(i + 1, (i + 1) & 1); CPWAIT1(); } else { CPWAIT0(); }
        __syncthreads();
        mma_blockT<8, 136>(&As[i & 1][0][0], &Bs[i & 1][0][0], acc, warp_m, warp_n, g_, t_);
        __syncthreads();
    }
#pragma unroll
    for (int mt = 0; mt < 2; mt++)
#pragma unroll
        for (int nt = 0; nt < 8; nt++) {
            int rl = warp_m * 32 + mt * 16 + g_;
            int c  = warp_n * 64 + nt * 8 + 2 * t_;
            float b0 = bskip[c], b1 = bskip[c + 1];
            if (m0 + rl < count) {
                int id = s_id[rl];
                *(float2*)&g_z[(size_t)id * 128 + c] =
                    make_float2(acc[mt][nt].x + b0, acc[mt][nt].y + b1);
            }
            if (m0 + rl + 8 < count) {
                int id = s_id[rl + 8];
                *(float2*)&g_z[(size_t)id * 128 + c] =
                    make_float2(acc[mt][nt].z + b0, acc[mt][nt].w + b1);
            }
        }
}

// ---------------- link predictor: 3x tf32 compensated (unpipelined) -----------
__global__ __launch_bounds__(256) void k_linkpred(
    const int* __restrict__ src, const int* __restrict__ dst,
    const float* __restrict__ Wls, const float* __restrict__ bls,
    const float* __restrict__ Wld, const float* __restrict__ bld,
    const float* __restrict__ Wlf, const float* __restrict__ blf,
    float* __restrict__ out)
{
    const int m0 = blockIdx.x * 128;
    const int tid = threadIdx.x, lane = tid & 31, wid = tid >> 5;
    const int warp_m = wid & 3, warp_n = wid >> 2, g_ = lane >> 2, t_ = lane & 3;

    __shared__ int s_src[128], s_dst[128];
    __shared__ uint32_t Ah[16][136], Al[16][136];
    __shared__ uint32_t Bh[16][136], Bl[16][136];
    __shared__ float out_s[128];

    if (tid < 128) {
        int e = min(m0 + tid, N_EVENTS - 1);
        s_src[tid] = src[e];
        s_dst[tid] = dst[e];
        out_s[tid] = 0.f;
    }
    __syncthreads();

    float4 acc[2][8];
#pragma unroll
    for (int i = 0; i < 2; i++)
#pragma unroll
        for (int j = 0; j < 8; j++) acc[i][j] = make_float4(0.f, 0.f, 0.f, 0.f);

    for (int k0 = 0; k0 < 256; k0 += 16) {
#pragma unroll
        for (int s = 0; s < 8; s++) {
            int idx = tid + s * 256;
            int kk = idx & 15, m = idx >> 4;
            int k = k0 + kk;
            float v = (k < 128) ? g_z[(size_t)s_src[m] * 128 + k]
                                : g_z[(size_t)s_dst[m] * 128 + (k - 128)];
            uint32_t h = f2tf32(v);
            Ah[kk][m] = h;
            Al[kk][m] = f2tf32(v - __uint_as_float(h));
        }
#pragma unroll
        for (int s = 0; s < 8; s++) {
            int idx = tid + s * 256;
            int kk = idx & 15, n = idx >> 4;
            int k = k0 + kk;
            float v = (k < 128) ? Wls[(size_t)n * 128 + k] : Wld[(size_t)n * 128 + (k - 128)];
            uint32_t h = f2tf32(v);
            Bh[kk][n] = h;
            Bl[kk][n] = f2tf32(v - __uint_as_float(h));
        }
        __syncthreads();
        mma_blockT<8, 136>(&Ah[0][0], &Bl[0][0], acc, warp_m, warp_n, g_, t_);
        mma_blockT<8, 136>(&Al[0][0], &Bh[0][0], acc, warp_m, warp_n, g_, t_);
        mma_blockT<8, 136>(&Ah[0][0], &Bh[0][0], acc, warp_m, warp_n, g_, t_);
        __syncthreads();
    }
    float p[4] = {0.f, 0.f, 0.f, 0.f};
#pragma unroll
    for (int mt = 0; mt < 2; mt++) {
#pragma unroll
        for (int nt = 0; nt < 8; nt++) {
            int c = warp_n * 64 + nt * 8 + 2 * t_;
            float bb0 = bls[c] + bld[c], bb1 = bls[c + 1] + bld[c + 1];
            float w0 = Wlf[c], w1 = Wlf[c + 1];
            p[mt * 2 + 0] += fmaxf(acc[mt][nt].x + bb0, 0.f) * w0
                           + fmaxf(acc[mt][nt].y + bb1, 0.f) * w1;
            p[mt * 2 + 1] += fmaxf(acc[mt][nt].z + bb0, 0.f) * w0
                           + fmaxf(acc[mt][nt].w + bb1, 0.f) * w1;
        }
    }
#pragma unroll
    for (int mt = 0; mt < 2; mt++) {
        int rl = warp_m * 32 + mt * 16 + g_;
        atomicAdd(&out_s[rl], p[mt * 2 + 0]);
        atomicAdd(&out_s[rl + 8], p[mt * 2 + 1]);
    }
    __syncthreads();
    if (tid < 128 && m0 + tid < N_EVENTS)
        out[m0 + tid] = out_s[tid] + blf[0];
}

// ---------------- launch -------------------------------------------------------
extern "C" void kernel_launch(void* const* d_in, const int* in_sizes, int n_in,
                              void* d_out, int out_size)
{
    const float* memory      = (const float*)d_in[0];
    const float* last_update = (const float*)d_in[1];
    const float* t           = (const float*)d_in[2];
    const float* msg         = (const float*)d_in[3];
    const int*   src         = (const int*)d_in[4];
    const int*   dst         = (const int*)d_in[5];
    const float* time_w      = (const float*)d_in[6];
    const float* time_b      = (const float*)d_in[7];
    const float* gru_Wih     = (const float*)d_in[8];
    const float* gru_bih     = (const float*)d_in[9];
    const float* gru_Whh     = (const float*)d_in[10];
    const float* gru_bhh     = (const float*)d_in[11];
    const float* Wq          = (const float*)d_in[12];
    const float* bq          = (const float*)d_in[13];
    const float* Wk          = (const float*)d_in[14];
    const float* bk          = (const float*)d_in[15];
    const float* Wv          = (const float*)d_in[16];
    const float* bv          = (const float*)d_in[17];
    const float* We          = (const float*)d_in[18];
    const float* Wskip       = (const float*)d_in[19];
    const float* bskip       = (const float*)d_in[20];
    const float* Wls         = (const float*)d_in[21];
    const float* bls         = (const float*)d_in[22];
    const float* Wld         = (const float*)d_in[23];
    const float* bld         = (const float*)d_in[24];
    const float* Wlf         = (const float*)d_in[25];
    const float* blf         = (const float*)d_in[26];
    float* out = (float*)d_out;

    k_init<<<(2 * N_NODES + 255) / 256, 256>>>();
    k_lastpos<<<(TWO_E + 255) / 256, 256>>>(src, dst);
    k_compact<<<(TWO_E + 255) / 256, 256>>>(src, dst, last_update, t);
    k_te_gru<<<(TWO_E * 64 + 255) / 256, 256>>>(last_update, t, src, dst, time_w, time_b);
    k_te_edge<<<(N_EVENTS * 64 + 255) / 256, 256>>>(t, src, time_w, time_b);
    {
        dim3 grid((TWO_E + 127) / 128, 4);
        k_gru<<<grid, 256>>>(memory, msg, src, dst, gru_Wih, gru_Whh, gru_bih, gru_bhh);
    }
    {
        dim3 grid((N_EVENTS + 127) / 128, 2);
        k_kv<<<grid, 256>>>(msg, src, Wk, bk, Wv, bv, We);
    }
    k_q<<<(N_EVENTS + 127) / 128, 256>>>(dst, Wq, bq);
    k_expsum<<<(N_EVENTS * 2 + 255) / 256, 256>>>(dst);
    k_skip<<<(TWO_E + 127) / 128, 256>>>(src, dst, Wskip, bskip);
    k_scatter<<<N_EVENTS, 128>>>(dst);
    k_linkpred<<<(N_EVENTS + 127) / 128, 256>>>(src, dst, Wls, bls, Wld, bld, Wlf, blf, out);
}

// round 11
// speedup vs baseline: 1.8253x; 1.7559x over previous
#include <cuda_runtime.h>
#include <cuda_fp16.h>
#include <math.h>
#include <stdint.h>

#define N_NODES 200000
#define N_EVENTS 50000
#define TWO_E (2 * N_EVENTS)

__device__ int      g_last_pos[N_NODES];
__device__ int      g_sel[TWO_E];
__device__ int      g_count;
__device__ float    g_mem_new[(size_t)N_NODES * 128];
__device__ float    g_lu_new[N_NODES];
__device__ float    g_kv[(size_t)N_EVENTS * 256];
__device__ float    g_logit[N_EVENTS * 2];
__device__ float    g_aexp[N_EVENTS * 2];
__device__ unsigned g_mx[N_NODES * 2];
__device__ float    g_denom[N_NODES * 2];
__device__ float    g_z[(size_t)N_NODES * 128];
__device__ float    g_te[(size_t)TWO_E * 64];
__device__ float    g_te2[(size_t)N_EVENTS * 64];

__device__ __forceinline__ unsigned enc_f(float x) {
    unsigned u = __float_as_uint(x);
    return (u & 0x80000000u) ? ~u : (u | 0x80000000u);
}
__device__ __forceinline__ float dec_f(unsigned u) {
    unsigned v = (u & 0x80000000u) ? (u & 0x7FFFFFFFu) : ~u;
    return __uint_as_float(v);
}
__device__ __forceinline__ float sigmoidf_(float x) { return 1.f / (1.f + expf(-x)); }
__device__ __forceinline__ uint32_t h2(float a, float b) {
    __half2 h = __floats2half2_rn(a, b);
    return *(uint32_t*)&h;
}

__device__ __forceinline__ void mma_f16(float4& d, const uint32_t a[4], const uint32_t b[2]) {
    asm volatile(
        "mma.sync.aligned.m16n8k16.row.col.f32.f16.f16.f32 "
        "{%0,%1,%2,%3}, {%4,%5,%6,%7}, {%8,%9}, {%0,%1,%2,%3};\n"
        : "+f"(d.x), "+f"(d.y), "+f"(d.z), "+f"(d.w)
        : "r"(a[0]), "r"(a[1]), "r"(a[2]), "r"(a[3]), "r"(b[0]), "r"(b[1]));
}

// one BK=32 tile step. A: [128][17] half2-words (16 cols + 1 pad).
// B: [N][17]. NT n-subtiles per warp.
template<int NT>
__device__ __forceinline__ void mma_blk(const uint32_t* __restrict__ As2,
                                        const uint32_t* __restrict__ Bs2,
                                        float4 (*acc)[NT],
                                        int warp_m, int warp_n, int g_, int t_)
{
#pragma unroll
    for (int ks = 0; ks < 2; ks++) {
        const int kc = ks * 8;
        uint32_t a[2][4], b[NT][2];
#pragma unroll
        for (int mt = 0; mt < 2; mt++) {
            int rb = warp_m * 32 + mt * 16 + g_;
            a[mt][0] = As2[rb * 17 + kc + t_];
            a[mt][1] = As2[(rb + 8) * 17 + kc + t_];
            a[mt][2] = As2[rb * 17 + kc + t_ + 4];
            a[mt][3] = As2[(rb + 8) * 17 + kc + t_ + 4];
        }
#pragma unroll
        for (int nt = 0; nt < NT; nt++) {
            int cb = warp_n * (NT * 8) + nt * 8 + g_;
            b[nt][0] = Bs2[cb * 17 + kc + t_];
            b[nt][1] = Bs2[cb * 17 + kc + t_ + 4];
        }
#pragma unroll
        for (int mt = 0; mt < 2; mt++)
#pragma unroll
            for (int nt = 0; nt < NT; nt++) mma_f16(acc[mt][nt], a[mt], b[nt]);
    }
}

// ---------------- small kernels ----------------------------------------------
__global__ void k_init() {
    int i = blockIdx.x * blockDim.x + threadIdx.x;
    if (i < N_NODES) g_last_pos[i] = -1;
    if (i < 2 * N_NODES) { g_mx[i] = 0u; g_denom[i] = 0.f; }
    if (i == 0) g_count = 0;
}
__global__ void k_lastpos(const int* __restrict__ src, const int* __restrict__ dst) {
    int j = blockIdx.x * blockDim.x + threadIdx.x;
    if (j >= TWO_E) return;
    int id = (j < N_EVENTS) ? src[j] : dst[j - N_EVENTS];
    atomicMax(&g_last_pos[id], j);
}
__global__ void k_compact(const int* __restrict__ src, const int* __restrict__ dst,
                          const float* __restrict__ lu, const float* __restrict__ t) {
    int j = blockIdx.x * blockDim.x + threadIdx.x;
    if (j >= TWO_E) return;
    int e = (j < N_EVENTS) ? j : j - N_EVENTS;
    int id = (j < N_EVENTS) ? src[e] : dst[e];
    if (g_last_pos[id] == j) {
        int p = atomicAdd(&g_count, 1);
        g_sel[p] = j;
        g_lu_new[id] = fmaxf(lu[id], t[e]);
    }
}
__global__ void k_te_gru(const float* __restrict__ last_update, const float* __restrict__ t,
                         const int* __restrict__ src, const int* __restrict__ dst,
                         const float* __restrict__ time_w, const float* __restrict__ time_b)
{
    int i = blockIdx.x * blockDim.x + threadIdx.x;
    int m = i >> 6, j = i & 63;
    if (m >= g_count) return;
    int sel = g_sel[m];
    int e  = (sel < N_EVENTS) ? sel : sel - N_EVENTS;
    int id = (sel < N_EVENTS) ? src[e] : dst[e];
    float dt = t[e] - last_update[id];
    g_te[(size_t)m * 64 + j] = cosf(fmaf(dt, time_w[j], time_b[j]));
}
__global__ void k_te_edge(const float* __restrict__ t, const int* __restrict__ src,
                          const float* __restrict__ time_w, const float* __restrict__ time_b)
{
    int i = blockIdx.x * blockDim.x + threadIdx.x;
    if (i >= N_EVENTS * 64) return;
    int e = i >> 6, j = i & 63;
    float rt = g_lu_new[src[e]] - t[e];
    g_te2[i] = cosf(fmaf(rt, time_w[j], time_b[j]));
}
__global__ void k_expsum(const int* __restrict__ dst) {
    int i = blockIdx.x * blockDim.x + threadIdx.x;
    if (i >= N_EVENTS * 2) return;
    int e = i >> 1, h = i & 1;
    int dn = dst[e];
    float a = expf(g_logit[i] - dec_f(g_mx[dn * 2 + h]));
    g_aexp[i] = a;
    atomicAdd(&g_denom[dn * 2 + h], a);
}
__global__ void k_scatter(const int* __restrict__ dst) {
    int e = blockIdx.x, d = threadIdx.x;
    int dn = dst[e], h = d >> 6;
    float attn = g_aexp[e * 2 + h] / g_denom[dn * 2 + h];
    atomicAdd(&g_z[(size_t)dn * 128 + d], attn * g_kv[(size_t)e * 256 + 128 + d]);
}

// ---------------- GRU: fp16 MMA, fused gates, grid=(rows/128, 4) --------------
// virtual A(K=512) = [mem_id|mem_oth|msg|te|mem_id]; 16 BK=32 tiles.
// per tile gate slots: {0, 1, (k0<384 ? 2 : 3)}.
__global__ __launch_bounds__(256) void k_gru(
    const float* __restrict__ memory, const float* __restrict__ msg,
    const int* __restrict__ src, const int* __restrict__ dst,
    const float* __restrict__ Wih, const float* __restrict__ Whh,
    const float* __restrict__ bih, const float* __restrict__ bhh)
{
    const int count = g_count;
    const int m0 = blockIdx.x * 128;
    if (m0 >= count) return;
    const int q = blockIdx.y;
    const int tid = threadIdx.x, lane = tid & 31, wid = tid >> 5;
    const int warp_m = wid & 3, warp_n = wid >> 2, g_ = lane >> 2, t_ = lane & 3;

    __shared__ int s_id[128], s_oth[128], s_e[128], s_mm[128];
    __shared__ uint32_t As2[128 * 17];
    __shared__ uint32_t Bs2[3 * 32 * 17];

    if (tid < 128) {
        int mm = min(m0 + tid, count - 1);
        int j = g_sel[mm];
        int e = (j < N_EVENTS) ? j : j - N_EVENTS;
        s_id[tid]  = (j < N_EVENTS) ? src[e] : dst[e];
        s_oth[tid] = (j < N_EVENTS) ? dst[e] : src[e];
        s_e[tid] = e; s_mm[tid] = mm;
    }
    __syncthreads();

    float4 acc[4][2][2];
#pragma unroll
    for (int g = 0; g < 4; g++)
#pragma unroll
        for (int i = 0; i < 2; i++)
#pragma unroll
            for (int j = 0; j < 2; j++) acc[g][i][j] = make_float4(0.f, 0.f, 0.f, 0.f);

    for (int tile = 0; tile < 16; tile++) {
        const int k0 = tile * 32;
        // A: 128 x 16 half2
#pragma unroll
        for (int s = 0; s < 8; s++) {
            int idx = tid + s * 256;
            int c = idx & 15, m = idx >> 4;
            int k = k0 + 2 * c;
            float2 v;
            if (k < 128)      v = *(const float2*)&memory[(size_t)s_id[m] * 128 + k];
            else if (k < 256) v = *(const float2*)&memory[(size_t)s_oth[m] * 128 + (k - 128)];
            else if (k < 320) v = *(const float2*)&msg[(size_t)s_e[m] * 64 + (k - 256)];
            else if (k < 384) v = *(const float2*)&g_te[(size_t)s_mm[m] * 64 + (k - 320)];
            else              v = *(const float2*)&memory[(size_t)s_id[m] * 128 + (k - 384)];
            As2[m * 17 + c] = h2(v.x, v.y);
        }
        // B: 3 slots x 32 x 16 half2
#pragma unroll
        for (int s = 0; s < 6; s++) {
            int idx = tid + s * 256;
            int slot = idx >> 9;
            int n = (idx >> 4) & 31;
            int c = idx & 15;
            int k = k0 + 2 * c;
            int g = (slot < 2) ? slot : (k0 < 384 ? 2 : 3);
            int r = q * 32 + n;
            const float* p;
            if (g < 2)       p = (k < 384) ? &Wih[(size_t)(g * 128 + r) * 384 + k]
                                           : &Whh[(size_t)(g * 128 + r) * 128 + (k - 384)];
            else if (g == 2) p = &Wih[(size_t)(256 + r) * 384 + k];
            else             p = &Whh[(size_t)(256 + r) * 128 + (k - 384)];
            float2 v = *(const float2*)p;
            Bs2[slot * 544 + n * 17 + c] = h2(v.x, v.y);
        }
        __syncthreads();
        mma_blk<2>(As2, Bs2,        acc[0], warp_m, warp_n, g_, t_);
        mma_blk<2>(As2, Bs2 + 544,  acc[1], warp_m, warp_n, g_, t_);
        if (k0 < 384) mma_blk<2>(As2, Bs2 + 1088, acc[2], warp_m, warp_n, g_, t_);
        else          mma_blk<2>(As2, Bs2 + 1088, acc[3], warp_m, warp_n, g_, t_);
        __syncthreads();
    }

    // fused gates epilogue
#pragma unroll
    for (int mt = 0; mt < 2; mt++)
#pragma unroll
    for (int nt = 0; nt < 2; nt++) {
        int cl = warp_n * 16 + nt * 8 + 2 * t_;
        int d = q * 32 + cl;
        float br0 = bih[d] + bhh[d],             br1 = bih[d + 1] + bhh[d + 1];
        float bz0 = bih[128 + d] + bhh[128 + d], bz1 = bih[129 + d] + bhh[129 + d];
        float bi0 = bih[256 + d],                bi1 = bih[257 + d];
        float bn0 = bhh[256 + d],                bn1 = bhh[257 + d];
#pragma unroll
        for (int hf = 0; hf < 2; hf++) {
            int rl = warp_m * 32 + mt * 16 + g_ + hf * 8;
            int m = m0 + rl;
            if (m < count) {
                int id = s_id[rl];
                float2 h = *(const float2*)&memory[(size_t)id * 128 + d];
                float R0, R1, Z0, Z1, I0, I1, H0, H1;
                if (hf == 0) {
                    R0 = acc[0][mt][nt].x; R1 = acc[0][mt][nt].y;
                    Z0 = acc[1][mt][nt].x; Z1 = acc[1][mt][nt].y;
                    I0 = acc[2][mt][nt].x; I1 = acc[2][mt][nt].y;
                    H0 = acc[3][mt][nt].x; H1 = acc[3][mt][nt].y;
                } else {
                    R0 = acc[0][mt][nt].z; R1 = acc[0][mt][nt].w;
                    Z0 = acc[1][mt][nt].z; Z1 = acc[1][mt][nt].w;
                    I0 = acc[2][mt][nt].z; I1 = acc[2][mt][nt].w;
                    H0 = acc[3][mt][nt].z; H1 = acc[3][mt][nt].w;
                }
                float r0 = sigmoidf_(R0 + br0), z0 = sigmoidf_(Z0 + bz0);
                float n0 = tanhf(I0 + bi0 + r0 * (H0 + bn0));
                float r1 = sigmoidf_(R1 + br1), z1 = sigmoidf_(Z1 + bz1);
                float n1 = tanhf(I1 + bi1 + r1 * (H1 + bn1));
                float2 o;
                o.x = (1.f - z0) * n0 + z0 * h.x;
                o.y = (1.f - z1) * n1 + z1 * h.y;
                *(float2*)&g_mem_new[(size_t)id * 128 + d] = o;
            }
        }
    }
}

// ---------------- kv GEMM: [E x 256], fp16, grid=(E/128, 2) -------------------
__global__ __launch_bounds__(256) void k_kv(
    const float* __restrict__ msg, const int* __restrict__ src,
    const float* __restrict__ Wk, const float* __restrict__ bk,
    const float* __restrict__ Wv, const float* __restrict__ bv,
    const float* __restrict__ We)
{
    const int m0 = blockIdx.x * 128;
    const int bn0 = blockIdx.y * 128;
    const int tid = threadIdx.x, lane = tid & 31, wid = tid >> 5;
    const int warp_m = wid & 3, warp_n = wid >> 2, g_ = lane >> 2, t_ = lane & 3;

    __shared__ int s_src[128], s_ec[128];
    __shared__ uint32_t As2[128 * 17];
    __shared__ uint32_t Bs2[128 * 17];

    if (tid < 128) {
        int e = min(m0 + tid, N_EVENTS - 1);
        s_src[tid] = src[e]; s_ec[tid] = e;
    }
    __syncthreads();

    float4 acc[2][8];
#pragma unroll
    for (int i = 0; i < 2; i++)
#pragma unroll
        for (int j = 0; j < 8; j++) acc[i][j] = make_float4(0.f, 0.f, 0.f, 0.f);

    for (int tile = 0; tile < 8; tile++) {
        const int k0 = tile * 32;
#pragma unroll
        for (int s = 0; s < 8; s++) {
            int idx = tid + s * 256;
            int c = idx & 15, m = idx >> 4;
            int k = k0 + 2 * c;
            float2 v;
            if (k < 128)      v = *(const float2*)&g_mem_new[(size_t)s_src[m] * 128 + k];
            else if (k < 192) v = *(const float2*)&g_te2[(size_t)s_ec[m] * 64 + (k - 128)];
            else              v = *(const float2*)&msg[(size_t)s_ec[m] * 64 + (k - 192)];
            As2[m * 17 + c] = h2(v.x, v.y);
        }
#pragma unroll
        for (int s = 0; s < 8; s++) {
            int idx = tid + s * 256;
            int c = idx & 15, n = idx >> 4;
            int k = k0 + 2 * c;
            int o = bn0 + n;
            const float* p;
            if (o < 128) p = (k < 128) ? &Wk[(size_t)o * 128 + k] : &We[(size_t)o * 128 + (k - 128)];
            else { int o2 = o - 128;
                   p = (k < 128) ? &Wv[(size_t)o2 * 128 + k] : &We[(size_t)o2 * 128 + (k - 128)]; }
            float2 v = *(const float2*)p;
            Bs2[n * 17 + c] = h2(v.x, v.y);
        }
        __syncthreads();
        mma_blk<8>(As2, Bs2, acc, warp_m, warp_n, g_, t_);
        __syncthreads();
    }
#pragma unroll
    for (int mt = 0; mt < 2; mt++)
#pragma unroll
        for (int nt = 0; nt < 8; nt++) {
            int r0 = m0 + warp_m * 32 + mt * 16 + g_;
            int c  = bn0 + warp_n * 64 + nt * 8 + 2 * t_;
            float b0 = (c < 128) ? bk[c] : bv[c - 128];
            float b1 = (c + 1 < 128) ? bk[c + 1] : bv[c + 1 - 128];
            if (r0 < N_EVENTS)
                *(float2*)&g_kv[(size_t)r0 * 256 + c] =
                    make_float2(acc[mt][nt].x + b0, acc[mt][nt].y + b1);
            if (r0 + 8 < N_EVENTS)
                *(float2*)&g_kv[(size_t)(r0 + 8) * 256 + c] =
                    make_float2(acc[mt][nt].z + b0, acc[mt][nt].w + b1);
        }
}

// ---------------- q GEMM + fused logit + segment max --------------------------
__global__ __launch_bounds__(256) void k_q(
    const int* __restrict__ dst,
    const float* __restrict__ Wq, const float* __restrict__ bq)
{
    const int m0 = blockIdx.x * 128;
    const int tid = threadIdx.x, lane = tid & 31, wid = tid >> 5;
    const int warp_m = wid & 3, warp_n = wid >> 2, g_ = lane >> 2, t_ = lane & 3;

    __shared__ int s_dst[128];
    __shared__ uint32_t As2[128 * 17];
    __shared__ uint32_t Bs2[128 * 17];
    __shared__ float logit_s[256];

    if (tid < 128) s_dst[tid] = dst[min(m0 + tid, N_EVENTS - 1)];
    logit_s[tid] = 0.f;
    __syncthreads();

    float4 acc[2][8];
#pragma unroll
    for (int i = 0; i < 2; i++)
#pragma unroll
        for (int j = 0; j < 8; j++) acc[i][j] = make_float4(0.f, 0.f, 0.f, 0.f);

    for (int tile = 0; tile < 4; tile++) {
        const int k0 = tile * 32;
#pragma unroll
        for (int s = 0; s < 8; s++) {
            int idx = tid + s * 256;
            int c = idx & 15, m = idx >> 4;
            float2 v = *(const float2*)&g_mem_new[(size_t)s_dst[m] * 128 + k0 + 2 * c];
            As2[m * 17 + c] = h2(v.x, v.y);
        }
#pragma unroll
        for (int s = 0; s < 8; s++) {
            int idx = tid + s * 256;
            int c = idx & 15, n = idx >> 4;
            float2 v = *(const float2*)&Wq[(size_t)n * 128 + k0 + 2 * c];
            Bs2[n * 17 + c] = h2(v.x, v.y);
        }
        __syncthreads();
        mma_blk<8>(As2, Bs2, acc, warp_m, warp_n, g_, t_);
        __syncthreads();
    }
    // logit epilogue: head = warp_n
    float p[4] = {0.f, 0.f, 0.f, 0.f};
#pragma unroll
    for (int mt = 0; mt < 2; mt++) {
        int r0 = m0 + warp_m * 32 + mt * 16 + g_;
        int r0c = min(r0, N_EVENTS - 1);
        int r1c = min(r0 + 8, N_EVENTS - 1);
#pragma unroll
        for (int nt = 0; nt < 8; nt++) {
            int c = warp_n * 64 + nt * 8 + 2 * t_;
            float bq0 = bq[c], bq1 = bq[c + 1];
            p[mt * 2 + 0] += (acc[mt][nt].x + bq0) * g_kv[(size_t)r0c * 256 + c]
                           + (acc[mt][nt].y + bq1) * g_kv[(size_t)r0c * 256 + c + 1];
            p[mt * 2 + 1] += (acc[mt][nt].z + bq0) * g_kv[(size_t)r1c * 256 + c]
                           + (acc[mt][nt].w + bq1) * g_kv[(size_t)r1c * 256 + c + 1];
        }
    }
#pragma unroll
    for (int mt = 0; mt < 2; mt++) {
        int rl = warp_m * 32 + mt * 16 + g_;
        atomicAdd(&logit_s[rl * 2 + warp_n], p[mt * 2 + 0]);
        atomicAdd(&logit_s[(rl + 8) * 2 + warp_n], p[mt * 2 + 1]);
    }
    __syncthreads();
    {
        int rl = tid >> 1, h = tid & 1;
        int m = m0 + rl;
        if (m < N_EVENTS) {
            float lg = logit_s[tid] * 0.125f;
            g_logit[m * 2 + h] = lg;
            atomicMax(&g_mx[(size_t)s_dst[rl] * 2 + h], enc_f(lg));
        }
    }
}

// ---------------- skip GEMM over compacted nodes ------------------------------
__global__ __launch_bounds__(256) void k_skip(
    const int* __restrict__ src, const int* __restrict__ dst,
    const float* __restrict__ Wskip, const float* __restrict__ bskip)
{
    const int count = g_count;
    const int m0 = blockIdx.x * 128;
    if (m0 >= count) return;
    const int tid = threadIdx.x, lane = tid & 31, wid = tid >> 5;
    const int warp_m = wid & 3, warp_n = wid >> 2, g_ = lane >> 2, t_ = lane & 3;

    __shared__ int s_id[128];
    __shared__ uint32_t As2[128 * 17];
    __shared__ uint32_t Bs2[128 * 17];

    if (tid < 128) {
        int mm = min(m0 + tid, count - 1);
        int j = g_sel[mm];
        int e = (j < N_EVENTS) ? j : j - N_EVENTS;
        s_id[tid] = (j < N_EVENTS) ? src[e] : dst[e];
    }
    __syncthreads();

    float4 acc[2][8];
#pragma unroll
    for (int i = 0; i < 2; i++)
#pragma unroll
        for (int j = 0; j < 8; j++) acc[i][j] = make_float4(0.f, 0.f, 0.f, 0.f);

    for (int tile = 0; tile < 4; tile++) {
        const int k0 = tile * 32;
#pragma unroll
        for (int s = 0; s < 8; s++) {
            int idx = tid + s * 256;
            int c = idx & 15, m = idx >> 4;
            float2 v = *(const float2*)&g_mem_new[(size_t)s_id[m] * 128 + k0 + 2 * c];
            As2[m * 17 + c] = h2(v.x, v.y);
        }
#pragma unroll
        for (int s = 0; s < 8; s++) {
            int idx = tid + s * 256;
            int c = idx & 15, n = idx >> 4;
            float2 v = *(const float2*)&Wskip[(size_t)n * 128 + k0 + 2 * c];
            Bs2[n * 17 + c] = h2(v.x, v.y);
        }
        __syncthreads();
        mma_blk<8>(As2, Bs2, acc, warp_m, warp_n, g_, t_);
        __syncthreads();
    }
#pragma unroll
    for (int mt = 0; mt < 2; mt++)
#pragma unroll
        for (int nt = 0; nt < 8; nt++) {
            int rl = warp_m * 32 + mt * 16 + g_;
            int c  = warp_n * 64 + nt * 8 + 2 * t_;
            float b0 = bskip[c], b1 = bskip[c + 1];
            if (m0 + rl < count) {
                int id = s_id[rl];
                *(float2*)&g_z[(size_t)id * 128 + c] =
                    make_float2(acc[mt][nt].x + b0, acc[mt][nt].y + b1);
            }
            if (m0 + rl + 8 < count) {
                int id = s_id[rl + 8];
                *(float2*)&g_z[(size_t)id * 128 + c] =
                    make_float2(acc[mt][nt].z + b0, acc[mt][nt].w + b1);
            }
        }
}

// ---------------- link predictor: 3x fp16 compensated -------------------------
__global__ __launch_bounds__(256) void k_linkpred(
    const int* __restrict__ src, const int* __restrict__ dst,
    const float* __restrict__ Wls, const float* __restrict__ bls,
    const float* __restrict__ Wld, const float* __restrict__ bld,
    const float* __restrict__ Wlf, const float* __restrict__ blf,
    float* __restrict__ out)
{
    const int m0 = blockIdx.x * 128;
    const int tid = threadIdx.x, lane = tid & 31, wid = tid >> 5;
    const int warp_m = wid & 3, warp_n = wid >> 2, g_ = lane >> 2, t_ = lane & 3;

    __shared__ int s_src[128], s_dst[128];
    __shared__ uint32_t Ah2[128 * 17], Al2[128 * 17];
    __shared__ uint32_t Bh2[128 * 17], Bl2[128 * 17];
    __shared__ float out_s[128];

    if (tid < 128) {
        int e = min(m0 + tid, N_EVENTS - 1);
        s_src[tid] = src[e]; s_dst[tid] = dst[e];
        out_s[tid] = 0.f;
    }
    __syncthreads();

    float4 acc[2][8];
#pragma unroll
    for (int i = 0; i < 2; i++)
#pragma unroll
        for (int j = 0; j < 8; j++) acc[i][j] = make_float4(0.f, 0.f, 0.f, 0.f);

    for (int tile = 0; tile < 8; tile++) {
        const int k0 = tile * 32;
#pragma unroll
        for (int s = 0; s < 8; s++) {
            int idx = tid + s * 256;
            int c = idx & 15, m = idx >> 4;
            int k = k0 + 2 * c;
            float2 v = (k < 128) ? *(const float2*)&g_z[(size_t)s_src[m] * 128 + k]
                                 : *(const float2*)&g_z[(size_t)s_dst[m] * 128 + (k - 128)];
            __half2 hh = __floats2half2_rn(v.x, v.y);
            Ah2[m * 17 + c] = *(uint32_t*)&hh;
            float lx = v.x - __half2float(__low2half(hh));
            float ly = v.y - __half2float(__high2half(hh));
            Al2[m * 17 + c] = h2(lx, ly);
        }
#pragma unroll
        for (int s = 0; s < 8; s++) {
            int idx = tid + s * 256;
            int c = idx & 15, n = idx >> 4;
            int k = k0 + 2 * c;
            float2 v = (k < 128) ? *(const float2*)&Wls[(size_t)n * 128 + k]
                                 : *(const float2*)&Wld[(size_t)n * 128 + (k - 128)];
            __half2 hh = __floats2half2_rn(v.x, v.y);
            Bh2[n * 17 + c] = *(uint32_t*)&hh;
            float lx = v.x - __half2float(__low2half(hh));
            float ly = v.y - __half2float(__high2half(hh));
            Bl2[n * 17 + c] = h2(lx, ly);
        }
        __syncthreads();
        mma_blk<8>(Ah2, Bh2, acc, warp_m, warp_n, g_, t_);
        mma_blk<8>(Ah2, Bl2, acc, warp_m, warp_n, g_, t_);
        mma_blk<8>(Al2, Bh2, acc, warp_m, warp_n, g_, t_);
        __syncthreads();
    }
    float p[4] = {0.f, 0.f, 0.f, 0.f};
#pragma unroll
    for (int mt = 0; mt < 2; mt++) {
#pragma unroll
        for (int nt = 0; nt < 8; nt++) {
            int c = warp_n * 64 + nt * 8 + 2 * t_;
            float bb0 = bls[c] + bld[c], bb1 = bls[c + 1] + bld[c + 1];
            float w0 = Wlf[c], w1 = Wlf[c + 1];
            p[mt * 2 + 0] += fmaxf(acc[mt][nt].x + bb0, 0.f) * w0
                           + fmaxf(acc[mt][nt].y + bb1, 0.f) * w1;
            p[mt * 2 + 1] += fmaxf(acc[mt][nt].z + bb0, 0.f) * w0
                           + fmaxf(acc[mt][nt].w + bb1, 0.f) * w1;
        }
    }
#pragma unroll
    for (int mt = 0; mt < 2; mt++) {
        int rl = warp_m * 32 + mt * 16 + g_;
        atomicAdd(&out_s[rl], p[mt * 2 + 0]);
        atomicAdd(&out_s[rl + 8], p[mt * 2 + 1]);
    }
    __syncthreads();
    if (tid < 128 && m0 + tid < N_EVENTS)
        out[m0 + tid] = out_s[tid] + blf[0];
}

// ---------------- launch -------------------------------------------------------
extern "C" void kernel_launch(void* const* d_in, const int* in_sizes, int n_in,
                              void* d_out, int out_size)
{
    const float* memory      = (const float*)d_in[0];
    const float* last_update = (const float*)d_in[1];
    const float* t           = (const float*)d_in[2];
    const float* msg         = (const float*)d_in[3];
    const int*   src         = (const int*)d_in[4];
    const int*   dst         = (const int*)d_in[5];
    const float* time_w      = (const float*)d_in[6];
    const float* time_b      = (const float*)d_in[7];
    const float* gru_Wih     = (const float*)d_in[8];
    const float* gru_bih     = (const float*)d_in[9];
    const float* gru_Whh     = (const float*)d_in[10];
    const float* gru_bhh     = (const float*)d_in[11];
    const float* Wq          = (const float*)d_in[12];
    const float* bq          = (const float*)d_in[13];
    const float* Wk          = (const float*)d_in[14];
    const float* bk          = (const float*)d_in[15];
    const float* Wv          = (const float*)d_in[16];
    const float* bv          = (const float*)d_in[17];
    const float* We          = (const float*)d_in[18];
    const float* Wskip       = (const float*)d_in[19];
    const float* bskip       = (const float*)d_in[20];
    const float* Wls         = (const float*)d_in[21];
    const float* bls         = (const float*)d_in[22];
    const float* Wld         = (const float*)d_in[23];
    const float* bld         = (const float*)d_in[24];
    const float* Wlf         = (const float*)d_in[25];
    const float* blf         = (const float*)d_in[26];
    float* out = (float*)d_out;

    k_init<<<(2 * N_NODES + 255) / 256, 256>>>();
    k_lastpos<<<(TWO_E + 255) / 256, 256>>>(src, dst);
    k_compact<<<(TWO_E + 255) / 256, 256>>>(src, dst, last_update, t);
    k_te_gru<<<(TWO_E * 64 + 255) / 256, 256>>>(last_update, t, src, dst, time_w, time_b);
    k_te_edge<<<(N_EVENTS * 64 + 255) / 256, 256>>>(t, src, time_w, time_b);
    {
        dim3 grid((TWO_E + 127) / 128, 4);
        k_gru<<<grid, 256>>>(memory, msg, src, dst, gru_Wih, gru_Whh, gru_bih, gru_bhh);
    }
    {
        dim3 grid((N_EVENTS + 127) / 128, 2);
        k_kv<<<grid, 256>>>(msg, src, Wk, bk, Wv, bv, We);
    }
    k_q<<<(N_EVENTS + 127) / 128, 256>>>(dst, Wq, bq);
    k_expsum<<<(N_EVENTS * 2 + 255) / 256, 256>>>(dst);
    k_skip<<<(TWO_E + 127) / 128, 256>>>(src, dst, Wskip, bskip);
    k_scatter<<<N_EVENTS, 128>>>(dst);
    k_linkpred<<<(N_EVENTS + 127) / 128, 256>>>(src, dst, Wls, bls, Wld, bld, Wlf, blf, out);
}

// round 15
// speedup vs baseline: 1.8666x; 1.0226x over previous
#include <cuda_runtime.h>
#include <cuda_fp16.h>
#include <math.h>
#include <stdint.h>

#define N_NODES 200000
#define N_EVENTS 50000
#define TWO_E (2 * N_EVENTS)
#define PITCH 20   // words per smem row: 80B, 16B-aligned for ldmatrix

__device__ int      g_last_pos[N_NODES];
__device__ int      g_sel[TWO_E];
__device__ int      g_count;
__device__ float    g_mem_new[(size_t)N_NODES * 128];
__device__ float    g_lu_new[N_NODES];
__device__ float    g_kv[(size_t)N_EVENTS * 256];
__device__ float    g_logit[N_EVENTS * 2];
__device__ float    g_aexp[N_EVENTS * 2];
__device__ unsigned g_mx[N_NODES * 2];
__device__ float    g_denom[N_NODES * 2];
__device__ float    g_z[(size_t)N_NODES * 128];
__device__ float    g_te[(size_t)TWO_E * 64];
__device__ float    g_te2[(size_t)N_EVENTS * 64];

__device__ __forceinline__ unsigned enc_f(float x) {
    unsigned u = __float_as_uint(x);
    return (u & 0x80000000u) ? ~u : (u | 0x80000000u);
}
__device__ __forceinline__ float dec_f(unsigned u) {
    unsigned v = (u & 0x80000000u) ? (u & 0x7FFFFFFFu) : ~u;
    return __uint_as_float(v);
}
__device__ __forceinline__ float sigmoidf_(float x) { return 1.f / (1.f + expf(-x)); }
__device__ __forceinline__ uint32_t h2(float a, float b) {
    __half2 h = __floats2half2_rn(a, b);
    return *(uint32_t*)&h;
}
__device__ __forceinline__ uint32_t smem_u32(const void* p) {
    uint32_t a;
    asm("{ .reg .u64 t; cvta.to.shared.u64 t, %1; cvt.u32.u64 %0, t; }" : "=r"(a) : "l"(p));
    return a;
}

__device__ __forceinline__ void mma_f16(float4& d, const uint32_t a[4], const uint32_t b[2]) {
    asm volatile(
        "mma.sync.aligned.m16n8k16.row.col.f32.f16.f16.f32 "
        "{%0,%1,%2,%3}, {%4,%5,%6,%7}, {%8,%9}, {%0,%1,%2,%3};\n"
        : "+f"(d.x), "+f"(d.y), "+f"(d.z), "+f"(d.w)
        : "r"(a[0]), "r"(a[1]), "r"(a[2]), "r"(a[3]), "r"(b[0]), "r"(b[1]));
}

// one BK=32 tile step via ldmatrix. A tile: [128][PITCH] half2-words in smem.
// B tile: [N][PITCH]. NT n-subtiles per warp (NT even).
template<int NT>
__device__ __forceinline__ void mma_blk(uint32_t aBase, uint32_t bBase,
                                        float4 (*acc)[NT],
                                        int warp_m, int warp_n, int lane)
{
    const int rowA = warp_m * 32 + (lane & 15);
    const int hiA  = (lane >> 4) & 1;               // k-half select for A
    const int nB   = warp_n * (NT * 8) + (lane & 7) + ((lane & 16) ? 8 : 0);
    const int hB   = (lane & 8) ? 4 : 0;            // k-half select for B
#pragma unroll
    for (int ks = 0; ks < 2; ks++) {
        uint32_t a[2][4];
#pragma unroll
        for (int mt = 0; mt < 2; mt++) {
            uint32_t ad = aBase + (uint32_t)(((rowA + mt * 16) * PITCH + hiA * 4 + ks * 8) << 2);
            asm volatile("ldmatrix.sync.aligned.m8n8.x4.shared.b16 {%0,%1,%2,%3}, [%4];"
                : "=r"(a[mt][0]), "=r"(a[mt][1]), "=r"(a[mt][2]), "=r"(a[mt][3]) : "r"(ad));
        }
        uint32_t b[NT][2];
#pragma unroll
        for (int p = 0; p < NT / 2; p++) {
            uint32_t bd = bBase + (uint32_t)(((nB + p * 16) * PITCH + hB + ks * 8) << 2);
            asm volatile("ldmatrix.sync.aligned.m8n8.x4.shared.b16 {%0,%1,%2,%3}, [%4];"
                : "=r"(b[2 * p][0]), "=r"(b[2 * p][1]),
                  "=r"(b[2 * p + 1][0]), "=r"(b[2 * p + 1][1]) : "r"(bd));
        }
#pragma unroll
        for (int mt = 0; mt < 2; mt++)
#pragma unroll
            for (int nt = 0; nt < NT; nt++) mma_f16(acc[mt][nt], a[mt], b[nt]);
    }
}

// ---------------- small kernels ----------------------------------------------
__global__ void k_init() {
    int i = blockIdx.x * blockDim.x + threadIdx.x;
    if (i < N_NODES) g_last_pos[i] = -1;
    if (i < 2 * N_NODES) { g_mx[i] = 0u; g_denom[i] = 0.f; }
    if (i == 0) g_count = 0;
}
__global__ void k_lastpos(const int* __restrict__ src, const int* __restrict__ dst) {
    int j = blockIdx.x * blockDim.x + threadIdx.x;
    if (j >= TWO_E) return;
    int id = (j < N_EVENTS) ? src[j] : dst[j - N_EVENTS];
    atomicMax(&g_last_pos[id], j);
}
__global__ void k_compact(const int* __restrict__ src, const int* __restrict__ dst,
                          const float* __restrict__ lu, const float* __restrict__ t) {
    int j = blockIdx.x * blockDim.x + threadIdx.x;
    if (j >= TWO_E) return;
    int e = (j < N_EVENTS) ? j : j - N_EVENTS;
    int id = (j < N_EVENTS) ? src[e] : dst[e];
    if (g_last_pos[id] == j) {
        int p = atomicAdd(&g_count, 1);
        g_sel[p] = j;
        g_lu_new[id] = fmaxf(lu[id], t[e]);
    }
}
__global__ void k_te_gru(const float* __restrict__ last_update, const float* __restrict__ t,
                         const int* __restrict__ src, const int* __restrict__ dst,
                         const float* __restrict__ time_w, const float* __restrict__ time_b)
{
    int i = blockIdx.x * blockDim.x + threadIdx.x;
    int m = i >> 6, j = i & 63;
    if (m >= g_count) return;
    int sel = g_sel[m];
    int e  = (sel < N_EVENTS) ? sel : sel - N_EVENTS;
    int id = (sel < N_EVENTS) ? src[e] : dst[e];
    float dt = t[e] - last_update[id];
    g_te[(size_t)m * 64 + j] = cosf(fmaf(dt, time_w[j], time_b[j]));
}
__global__ void k_te_edge(const float* __restrict__ t, const int* __restrict__ src,
                          const float* __restrict__ time_w, const float* __restrict__ time_b)
{
    int i = blockIdx.x * blockDim.x + threadIdx.x;
    if (i >= N_EVENTS * 64) return;
    int e = i >> 6, j = i & 63;
    float rt = g_lu_new[src[e]] - t[e];
    g_te2[i] = cosf(fmaf(rt, time_w[j], time_b[j]));
}
__global__ void k_expsum(const int* __restrict__ dst) {
    int i = blockIdx.x * blockDim.x + threadIdx.x;
    if (i >= N_EVENTS * 2) return;
    int e = i >> 1, h = i & 1;
    int dn = dst[e];
    float a = expf(g_logit[i] - dec_f(g_mx[dn * 2 + h]));
    g_aexp[i] = a;
    atomicAdd(&g_denom[dn * 2 + h], a);
}
__global__ void k_scatter(const int* __restrict__ dst) {
    int e = blockIdx.x, d = threadIdx.x;
    int dn = dst[e], h = d >> 6;
    float attn = g_aexp[e * 2 + h] / g_denom[dn * 2 + h];
    atomicAdd(&g_z[(size_t)dn * 128 + d], attn * g_kv[(size_t)e * 256 + 128 + d]);
}

// ---------------- GRU: fp16 MMA, fused gates, grid=(rows/128, 4) --------------
__global__ __launch_bounds__(256) void k_gru(
    const float* __restrict__ memory, const float* __restrict__ msg,
    const int* __restrict__ src, const int* __restrict__ dst,
    const float* __restrict__ Wih, const float* __restrict__ Whh,
    const float* __restrict__ bih, const float* __restrict__ bhh)
{
    const int count = g_count;
    const int m0 = blockIdx.x * 128;
    if (m0 >= count) return;
    const int q = blockIdx.y;
    const int tid = threadIdx.x, lane = tid & 31, wid = tid >> 5;
    const int warp_m = wid & 3, warp_n = wid >> 2;

    __shared__ int s_id[128], s_oth[128], s_e[128], s_mm[128];
    __shared__ __align__(16) uint32_t As2[128 * PITCH];
    __shared__ __align__(16) uint32_t Bs2[3 * 32 * PITCH];
    const uint32_t aBase = smem_u32(As2);
    const uint32_t bBase = smem_u32(Bs2);

    if (tid < 128) {
        int mm = min(m0 + tid, count - 1);
        int j = g_sel[mm];
        int e = (j < N_EVENTS) ? j : j - N_EVENTS;
        s_id[tid]  = (j < N_EVENTS) ? src[e] : dst[e];
        s_oth[tid] = (j < N_EVENTS) ? dst[e] : src[e];
        s_e[tid] = e; s_mm[tid] = mm;
    }
    __syncthreads();

    float4 acc[4][2][2];
#pragma unroll
    for (int g = 0; g < 4; g++)
#pragma unroll
        for (int i = 0; i < 2; i++)
#pragma unroll
            for (int j = 0; j < 2; j++) acc[g][i][j] = make_float4(0.f, 0.f, 0.f, 0.f);

    for (int tile = 0; tile < 16; tile++) {
        const int k0 = tile * 32;
#pragma unroll
        for (int s = 0; s < 8; s++) {
            int idx = tid + s * 256;
            int c = idx & 15, m = idx >> 4;
            int k = k0 + 2 * c;
            float2 v;
            if (k < 128)      v = *(const float2*)&memory[(size_t)s_id[m] * 128 + k];
            else if (k < 256) v = *(const float2*)&memory[(size_t)s_oth[m] * 128 + (k - 128)];
            else if (k < 320) v = *(const float2*)&msg[(size_t)s_e[m] * 64 + (k - 256)];
            else if (k < 384) v = *(const float2*)&g_te[(size_t)s_mm[m] * 64 + (k - 320)];
            else              v = *(const float2*)&memory[(size_t)s_id[m] * 128 + (k - 384)];
            As2[m * PITCH + c] = h2(v.x, v.y);
        }
#pragma unroll
        for (int s = 0; s < 6; s++) {
            int idx = tid + s * 256;
            int slot = idx >> 9;
            int n = (idx >> 4) & 31;
            int c = idx & 15;
            int k = k0 + 2 * c;
            int g = (slot < 2) ? slot : (k0 < 384 ? 2 : 3);
            int r = q * 32 + n;
            const float* p;
            if (g < 2)       p = (k < 384) ? &Wih[(size_t)(g * 128 + r) * 384 + k]
                                           : &Whh[(size_t)(g * 128 + r) * 128 + (k - 384)];
            else if (g == 2) p = &Wih[(size_t)(256 + r) * 384 + k];
            else             p = &Whh[(size_t)(256 + r) * 128 + (k - 384)];
            float2 v = *(const float2*)p;
            Bs2[slot * (32 * PITCH) + n * PITCH + c] = h2(v.x, v.y);
        }
        __syncthreads();
        mma_blk<2>(aBase, bBase,                         acc[0], warp_m, warp_n, lane);
        mma_blk<2>(aBase, bBase + 32 * PITCH * 4,        acc[1], warp_m, warp_n, lane);
        if (k0 < 384) mma_blk<2>(aBase, bBase + 64 * PITCH * 4, acc[2], warp_m, warp_n, lane);
        else          mma_blk<2>(aBase, bBase + 64 * PITCH * 4, acc[3], warp_m, warp_n, lane);
        __syncthreads();
    }

    // fused gates epilogue
    const int g_ = lane >> 2, t_ = lane & 3;
#pragma unroll
    for (int mt = 0; mt < 2; mt++)
#pragma unroll
    for (int nt = 0; nt < 2; nt++) {
        int cl = warp_n * 16 + nt * 8 + 2 * t_;
        int d = q * 32 + cl;
        float br0 = bih[d] + bhh[d],             br1 = bih[d + 1] + bhh[d + 1];
        float bz0 = bih[128 + d] + bhh[128 + d], bz1 = bih[129 + d] + bhh[129 + d];
        float bi0 = bih[256 + d],                bi1 = bih[257 + d];
        float bn0 = bhh[256 + d],                bn1 = bhh[257 + d];
#pragma unroll
        for (int hf = 0; hf < 2; hf++) {
            int rl = warp_m * 32 + mt * 16 + g_ + hf * 8;
            int m = m0 + rl;
            if (m < count) {
                int id = s_id[rl];
                float2 h = *(const float2*)&memory[(size_t)id * 128 + d];
                float R0, R1, Z0, Z1, I0, I1, H0, H1;
                if (hf == 0) {
                    R0 = acc[0][mt][nt].x; R1 = acc[0][mt][nt].y;
                    Z0 = acc[1][mt][nt].x; Z1 = acc[1][mt][nt].y;
                    I0 = acc[2][mt][nt].x; I1 = acc[2][mt][nt].y;
                    H0 = acc[3][mt][nt].x; H1 = acc[3][mt][nt].y;
                } else {
                    R0 = acc[0][mt][nt].z; R1 = acc[0][mt][nt].w;
                    Z0 = acc[1][mt][nt].z; Z1 = acc[1][mt][nt].w;
                    I0 = acc[2][mt][nt].z; I1 = acc[2][mt][nt].w;
                    H0 = acc[3][mt][nt].z; H1 = acc[3][mt][nt].w;
                }
                float r0 = sigmoidf_(R0 + br0), z0 = sigmoidf_(Z0 + bz0);
                float n0 = tanhf(I0 + bi0 + r0 * (H0 + bn0));
                float r1 = sigmoidf_(R1 + br1), z1 = sigmoidf_(Z1 + bz1);
                float n1 = tanhf(I1 + bi1 + r1 * (H1 + bn1));
                float2 o;
                o.x = (1.f - z0) * n0 + z0 * h.x;
                o.y = (1.f - z1) * n1 + z1 * h.y;
                *(float2*)&g_mem_new[(size_t)id * 128 + d] = o;
            }
        }
    }
}

// ---------------- kv GEMM: [E x 256], fp16, grid=(E/128, 2) -------------------
__global__ __launch_bounds__(256) void k_kv(
    const float* __restrict__ msg, const int* __restrict__ src,
    const float* __restrict__ Wk, const float* __restrict__ bk,
    const float* __restrict__ Wv, const float* __restrict__ bv,
    const float* __restrict__ We)
{
    const int m0 = blockIdx.x * 128;
    const int bn0 = blockIdx.y * 128;
    const int tid = threadIdx.x, lane = tid & 31, wid = tid >> 5;
    const int warp_m = wid & 3, warp_n = wid >> 2, g_ = lane >> 2, t_ = lane & 3;

    __shared__ int s_src[128], s_ec[128];
    __shared__ __align__(16) uint32_t As2[128 * PITCH];
    __shared__ __align__(16) uint32_t Bs2[128 * PITCH];
    const uint32_t aBase = smem_u32(As2);
    const uint32_t bBase = smem_u32(Bs2);

    if (tid < 128) {
        int e = min(m0 + tid, N_EVENTS - 1);
        s_src[tid] = src[e]; s_ec[tid] = e;
    }
    __syncthreads();

    float4 acc[2][8];
#pragma unroll
    for (int i = 0; i < 2; i++)
#pragma unroll
        for (int j = 0; j < 8; j++) acc[i][j] = make_float4(0.f, 0.f, 0.f, 0.f);

    for (int tile = 0; tile < 8; tile++) {
        const int k0 = tile * 32;
#pragma unroll
        for (int s = 0; s < 8; s++) {
            int idx = tid + s * 256;
            int c = idx & 15, m = idx >> 4;
            int k = k0 + 2 * c;
            float2 v;
            if (k < 128)      v = *(const float2*)&g_mem_new[(size_t)s_src[m] * 128 + k];
            else if (k < 192) v = *(const float2*)&g_te2[(size_t)s_ec[m] * 64 + (k - 128)];
            else              v = *(const float2*)&msg[(size_t)s_ec[m] * 64 + (k - 192)];
            As2[m * PITCH + c] = h2(v.x, v.y);
        }
#pragma unroll
        for (int s = 0; s < 8; s++) {
            int idx = tid + s * 256;
            int c = idx & 15, n = idx >> 4;
            int k = k0 + 2 * c;
            int o = bn0 + n;
            const float* p;
            if (o < 128) p = (k < 128) ? &Wk[(size_t)o * 128 + k] : &We[(size_t)o * 128 + (k - 128)];
            else { int o2 = o - 128;
                   p = (k < 128) ? &Wv[(size_t)o2 * 128 + k] : &We[(size_t)o2 * 128 + (k - 128)]; }
            float2 v = *(const float2*)p;
            Bs2[n * PITCH + c] = h2(v.x, v.y);
        }
        __syncthreads();
        mma_blk<8>(aBase, bBase, acc, warp_m, warp_n, lane);
        __syncthreads();
    }
#pragma unroll
    for (int mt = 0; mt < 2; mt++)
#pragma unroll
        for (int nt = 0; nt < 8; nt++) {
            int r0 = m0 + warp_m * 32 + mt * 16 + g_;
            int c  = bn0 + warp_n * 64 + nt * 8 + 2 * t_;
            float b0 = (c < 128) ? bk[c] : bv[c - 128];
            float b1 = (c + 1 < 128) ? bk[c + 1] : bv[c + 1 - 128];
            if (r0 < N_EVENTS)
                *(float2*)&g_kv[(size_t)r0 * 256 + c] =
                    make_float2(acc[mt][nt].x + b0, acc[mt][nt].y + b1);
            if (r0 + 8 < N_EVENTS)
                *(float2*)&g_kv[(size_t)(r0 + 8) * 256 + c] =
                    make_float2(acc[mt][nt].z + b0, acc[mt][nt].w + b1);
        }
}

// ---------------- q GEMM + fused logit + segment max --------------------------
__global__ __launch_bounds__(256) void k_q(
    const int* __restrict__ dst,
    const float* __restrict__ Wq, const float* __restrict__ bq)
{
    const int m0 = blockIdx.x * 128;
    const int tid = threadIdx.x, lane = tid & 31, wid = tid >> 5;
    const int warp_m = wid & 3, warp_n = wid >> 2, g_ = lane >> 2, t_ = lane & 3;

    __shared__ int s_dst[128];
    __shared__ __align__(16) uint32_t As2[128 * PITCH];
    __shared__ __align__(16) uint32_t Bs2[128 * PITCH];
    __shared__ float logit_s[256];
    const uint32_t aBase = smem_u32(As2);
    const uint32_t bBase = smem_u32(Bs2);

    if (tid < 128) s_dst[tid] = dst[min(m0 + tid, N_EVENTS - 1)];
    logit_s[tid] = 0.f;
    __syncthreads();

    float4 acc[2][8];
#pragma unroll
    for (int i = 0; i < 2; i++)
#pragma unroll
        for (int j = 0; j < 8; j++) acc[i][j] = make_float4(0.f, 0.f, 0.f, 0.f);

    for (int tile = 0; tile < 4; tile++) {
        const int k0 = tile * 32;
#pragma unroll
        for (int s = 0; s < 8; s++) {
            int idx = tid + s * 256;
            int c = idx & 15, m = idx >> 4;
            float2 v = *(const float2*)&g_mem_new[(size_t)s_dst[m] * 128 + k0 + 2 * c];
            As2[m * PITCH + c] = h2(v.x, v.y);
        }
#pragma unroll
        for (int s = 0; s < 8; s++) {
            int idx = tid + s * 256;
            int c = idx & 15, n = idx >> 4;
            float2 v = *(const float2*)&Wq[(size_t)n * 128 + k0 + 2 * c];
            Bs2[n * PITCH + c] = h2(v.x, v.y);
        }
        __syncthreads();
        mma_blk<8>(aBase, bBase, acc, warp_m, warp_n, lane);
        __syncthreads();
    }
    float p[4] = {0.f, 0.f, 0.f, 0.f};
#pragma unroll
    for (int mt = 0; mt < 2; mt++) {
        int r0 = m0 + warp_m * 32 + mt * 16 + g_;
        int r0c = min(r0, N_EVENTS - 1);
        int r1c = min(r0 + 8, N_EVENTS - 1);
#pragma unroll
        for (int nt = 0; nt < 8; nt++) {
            int c = warp_n * 64 + nt * 8 + 2 * t_;
            float bq0 = bq[c], bq1 = bq[c + 1];
            p[mt * 2 + 0] += (acc[mt][nt].x + bq0) * g_kv[(size_t)r0c * 256 + c]
                           + (acc[mt][nt].y + bq1) * g_kv[(size_t)r0c * 256 + c + 1];
            p[mt * 2 + 1] += (acc[mt][nt].z + bq0) * g_kv[(size_t)r1c * 256 + c]
                           + (acc[mt][nt].w + bq1) * g_kv[(size_t)r1c * 256 + c + 1];
        }
    }
#pragma unroll
    for (int mt = 0; mt < 2; mt++) {
        int rl = warp_m * 32 + mt * 16 + g_;
        atomicAdd(&logit_s[rl * 2 + warp_n], p[mt * 2 + 0]);
        atomicAdd(&logit_s[(rl + 8) * 2 + warp_n], p[mt * 2 + 1]);
    }
    __syncthreads();
    {
        int rl = tid >> 1, h = tid & 1;
        int m = m0 + rl;
        if (m < N_EVENTS) {
            float lg = logit_s[tid] * 0.125f;
            g_logit[m * 2 + h] = lg;
            atomicMax(&g_mx[(size_t)s_dst[rl] * 2 + h], enc_f(lg));
        }
    }
}

// ---------------- skip GEMM over compacted nodes ------------------------------
__global__ __launch_bounds__(256) void k_skip(
    const int* __restrict__ src, const int* __restrict__ dst,
    const float* __restrict__ Wskip, const float* __restrict__ bskip)
{
    const int count = g_count;
    const int m0 = blockIdx.x * 128;
    if (m0 >= count) return;
    const int tid = threadIdx.x, lane = tid & 31, wid = tid >> 5;
    const int warp_m = wid & 3, warp_n = wid >> 2, g_ = lane >> 2, t_ = lane & 3;

    __shared__ int s_id[128];
    __shared__ __align__(16) uint32_t As2[128 * PITCH];
    __shared__ __align__(16) uint32_t Bs2[128 * PITCH];
    const uint32_t aBase = smem_u32(As2);
    const uint32_t bBase = smem_u32(Bs2);

    if (tid < 128) {
        int mm = min(m0 + tid, count - 1);
        int j = g_sel[mm];
        int e = (j < N_EVENTS) ? j : j - N_EVENTS;
        s_id[tid] = (j < N_EVENTS) ? src[e] : dst[e];
    }
    __syncthreads();

    float4 acc[2][8];
#pragma unroll
    for (int i = 0; i < 2; i++)
#pragma unroll
        for (int j = 0; j < 8; j++) acc[i][j] = make_float4(0.f, 0.f, 0.f, 0.f);

    for (int tile = 0; tile < 4; tile++) {
        const int k0 = tile * 32;
#pragma unroll
        for (int s = 0; s < 8; s++) {
            int idx = tid + s * 256;
            int c = idx & 15, m = idx >> 4;
            float2 v = *(const float2*)&g_mem_new[(size_t)s_id[m] * 128 + k0 + 2 * c];
            As2[m * PITCH + c] = h2(v.x, v.y);
        }
#pragma unroll
        for (int s = 0; s < 8; s++) {
            int idx = tid + s * 256;
            int c = idx & 15, n = idx >> 4;
            float2 v = *(const float2*)&Wskip[(size_t)n * 128 + k0 + 2 * c];
            Bs2[n * PITCH + c] = h2(v.x, v.y);
        }
        __syncthreads();
        mma_blk<8>(aBase, bBase, acc, warp_m, warp_n, lane);
        __syncthreads();
    }
#pragma unroll
    for (int mt = 0; mt < 2; mt++)
#pragma unroll
        for (int nt = 0; nt < 8; nt++) {
            int rl = warp_m * 32 + mt * 16 + g_;
            int c  = warp_n * 64 + nt * 8 + 2 * t_;
            float b0 = bskip[c], b1 = bskip[c + 1];
            if (m0 + rl < count) {
                int id = s_id[rl];
                *(float2*)&g_z[(size_t)id * 128 + c] =
                    make_float2(acc[mt][nt].x + b0, acc[mt][nt].y + b1);
            }
            if (m0 + rl + 8 < count) {
                int id = s_id[rl + 8];
                *(float2*)&g_z[(size_t)id * 128 + c] =
                    make_float2(acc[mt][nt].z + b0, acc[mt][nt].w + b1);
            }
        }
}

// ---------------- link predictor: 3x fp16 compensated -------------------------
__global__ __launch_bounds__(256) void k_linkpred(
    const int* __restrict__ src, const int* __restrict__ dst,
    const float* __restrict__ Wls, const float* __restrict__ bls,
    const float* __restrict__ Wld, const float* __restrict__ bld,
    const float* __restrict__ Wlf, const float* __restrict__ blf,
    float* __restrict__ out)
{
    const int m0 = blockIdx.x * 128;
    const int tid = threadIdx.x, lane = tid & 31, wid = tid >> 5;
    const int warp_m = wid & 3, warp_n = wid >> 2, g_ = lane >> 2, t_ = lane & 3;

    __shared__ int s_src[128], s_dst[128];
    __shared__ __align__(16) uint32_t Ah2[128 * PITCH];
    __shared__ __align__(16) uint32_t Al2[128 * PITCH];
    __shared__ __align__(16) uint32_t Bh2[128 * PITCH];
    __shared__ __align__(16) uint32_t Bl2[128 * PITCH];
    __shared__ float out_s[128];
    const uint32_t ahB = smem_u32(Ah2), alB = smem_u32(Al2);
    const uint32_t bhB = smem_u32(Bh2), blB = smem_u32(Bl2);

    if (tid < 128) {
        int e = min(m0 + tid, N_EVENTS - 1);
        s_src[tid] = src[e]; s_dst[tid] = dst[e];
        out_s[tid] = 0.f;
    }
    __syncthreads();

    float4 acc[2][8];
#pragma unroll
    for (int i = 0; i < 2; i++)
#pragma unroll
        for (int j = 0; j < 8; j++) acc[i][j] = make_float4(0.f, 0.f, 0.f, 0.f);

    for (int tile = 0; tile < 8; tile++) {
        const int k0 = tile * 32;
#pragma unroll
        for (int s = 0; s < 8; s++) {
            int idx = tid + s * 256;
            int c = idx & 15, m = idx >> 4;
            int k = k0 + 2 * c;
            float2 v = (k < 128) ? *(const float2*)&g_z[(size_t)s_src[m] * 128 + k]
                                 : *(const float2*)&g_z[(size_t)s_dst[m] * 128 + (k - 128)];
            __half2 hh = __floats2half2_rn(v.x, v.y);
            Ah2[m * PITCH + c] = *(uint32_t*)&hh;
            float lx = v.x - __half2float(__low2half(hh));
            float ly = v.y - __half2float(__high2half(hh));
            Al2[m * PITCH + c] = h2(lx, ly);
        }
#pragma unroll
        for (int s = 0; s < 8; s++) {
            int idx = tid + s * 256;
            int c = idx & 15, n = idx >> 4;
            int k = k0 + 2 * c;
            float2 v = (k < 128) ? *(const float2*)&Wls[(size_t)n * 128 + k]
                                 : *(const float2*)&Wld[(size_t)n * 128 + (k - 128)];
            __half2 hh = __floats2half2_rn(v.x, v.y);
            Bh2[n * PITCH + c] = *(uint32_t*)&hh;
            float lx = v.x - __half2float(__low2half(hh));
            float ly = v.y - __half2float(__high2half(hh));
            Bl2[n * PITCH + c] = h2(lx, ly);
        }
        __syncthreads();
        mma_blk<8>(ahB, bhB, acc, warp_m, warp_n, lane);
        mma_blk<8>(ahB, blB, acc, warp_m, warp_n, lane);
        mma_blk<8>(alB, bhB, acc, warp_m, warp_n, lane);
        __syncthreads();
    }
    float p[4] = {0.f, 0.f, 0.f, 0.f};
#pragma unroll
    for (int mt = 0; mt < 2; mt++) {
#pragma unroll
        for (int nt = 0; nt < 8; nt++) {
            int c = warp_n * 64 + nt * 8 + 2 * t_;
            float bb0 = bls[c] + bld[c], bb1 = bls[c + 1] + bld[c + 1];
            float w0 = Wlf[c], w1 = Wlf[c + 1];
            p[mt * 2 + 0] += fmaxf(acc[mt][nt].x + bb0, 0.f) * w0
                           + fmaxf(acc[mt][nt].y + bb1, 0.f) * w1;
            p[mt * 2 + 1] += fmaxf(acc[mt][nt].z + bb0, 0.f) * w0
                           + fmaxf(acc[mt][nt].w + bb1, 0.f) * w1;
        }
    }
#pragma unroll
    for (int mt = 0; mt < 2; mt++) {
        int rl = warp_m * 32 + mt * 16 + g_;
        atomicAdd(&out_s[rl], p[mt * 2 + 0]);
        atomicAdd(&out_s[rl + 8], p[mt * 2 + 1]);
    }
    __syncthreads();
    if (tid < 128 && m0 + tid < N_EVENTS)
        out[m0 + tid] = out_s[tid] + blf[0];
}

// ---------------- launch -------------------------------------------------------
extern "C" void kernel_launch(void* const* d_in, const int* in_sizes, int n_in,
                              void* d_out, int out_size)
{
    const float* memory      = (const float*)d_in[0];
    const float* last_update = (const float*)d_in[1];
    const float* t           = (const float*)d_in[2];
    const float* msg         = (const float*)d_in[3];
    const int*   src         = (const int*)d_in[4];
    const int*   dst         = (const int*)d_in[5];
    const float* time_w      = (const float*)d_in[6];
    const float* time_b      = (const float*)d_in[7];
    const float* gru_Wih     = (const float*)d_in[8];
    const float* gru_bih     = (const float*)d_in[9];
    const float* gru_Whh     = (const float*)d_in[10];
    const float* gru_bhh     = (const float*)d_in[11];
    const float* Wq          = (const float*)d_in[12];
    const float* bq          = (const float*)d_in[13];
    const float* Wk          = (const float*)d_in[14];
    const float* bk          = (const float*)d_in[15];
    const float* Wv          = (const float*)d_in[16];
    const float* bv          = (const float*)d_in[17];
    const float* We          = (const float*)d_in[18];
    const float* Wskip       = (const float*)d_in[19];
    const float* bskip       = (const float*)d_in[20];
    const float* Wls         = (const float*)d_in[21];
    const float* bls         = (const float*)d_in[22];
    const float* Wld         = (const float*)d_in[23];
    const float* bld         = (const float*)d_in[24];
    const float* Wlf         = (const float*)d_in[25];
    const float* blf         = (const float*)d_in[26];
    float* out = (float*)d_out;

    k_init<<<(2 * N_NODES + 255) / 256, 256>>>();
    k_lastpos<<<(TWO_E + 255) / 256, 256>>>(src, dst);
    k_compact<<<(TWO_E + 255) / 256, 256>>>(src, dst, last_update, t);
    k_te_gru<<<(TWO_E * 64 + 255) / 256, 256>>>(last_update, t, src, dst, time_w, time_b);
    k_te_edge<<<(N_EVENTS * 64 + 255) / 256, 256>>>(t, src, time_w, time_b);
    {
        dim3 grid((TWO_E + 127) / 128, 4);
        k_gru<<<grid, 256>>>(memory, msg, src, dst, gru_Wih, gru_Whh, gru_bih, gru_bhh);
    }
    {
        dim3 grid((N_EVENTS + 127) / 128, 2);
        k_kv<<<grid, 256>>>(msg, src, Wk, bk, Wv, bv, We);
    }
    k_q<<<(N_EVENTS + 127) / 128, 256>>>(dst, Wq, bq);
    k_expsum<<<(N_EVENTS * 2 + 255) / 256, 256>>>(dst);
    k_skip<<<(TWO_E + 127) / 128, 256>>>(src, dst, Wskip, bskip);
    k_scatter<<<N_EVENTS, 128>>>(dst);
    k_linkpred<<<(N_EVENTS + 127) / 128, 256>>>(src, dst, Wls, bls, Wld, bld, Wlf, blf, out);
}

// round 16
// speedup vs baseline: 2.4217x; 1.2974x over previous
#include <cuda_runtime.h>
#include <cuda_fp16.h>
#include <math.h>
#include <stdint.h>

#define N_NODES 200000
#define N_EVENTS 50000
#define TWO_E (2 * N_EVENTS)
#define PITCH 20   // words per smem row: 80B, 16B-aligned for ldmatrix

__device__ int      g_last_pos[N_NODES];
__device__ int      g_sel[TWO_E];
__device__ int      g_count;
__device__ float    g_lu_new[N_NODES];
__device__ float    g_kv[(size_t)N_EVENTS * 256];
__device__ float    g_logit[N_EVENTS * 2];
__device__ float    g_aexp[N_EVENTS * 2];
__device__ unsigned g_mx[N_NODES * 2];
__device__ float    g_denom[N_NODES * 2];
__device__ float    g_z[(size_t)N_NODES * 128];

// fp16 staging sources (precomputed once per launch)
__device__ __half g_mem_h[(size_t)N_NODES * 128];
__device__ __half g_memnew_h[(size_t)N_NODES * 128];
__device__ __half g_msg_h[(size_t)N_EVENTS * 64];
__device__ __half g_te_h[(size_t)TWO_E * 64];
__device__ __half g_te2_h[(size_t)N_EVENTS * 64];
__device__ __half g_wcomb[512 * 384];     // GRU combined weight (4 gates x 128 rows, K=384)
__device__ __half g_wkv[256 * 256];       // [Wk|We ; Wv|We]
__device__ __half g_wq[128 * 128];
__device__ __half g_wskip[128 * 128];
__device__ __half g_wl[128 * 256];        // [Wls|Wld] hi
__device__ __half g_wl_lo[128 * 256];     // lo residual

__device__ __forceinline__ unsigned enc_f(float x) {
    unsigned u = __float_as_uint(x);
    return (u & 0x80000000u) ? ~u : (u | 0x80000000u);
}
__device__ __forceinline__ float dec_f(unsigned u) {
    unsigned v = (u & 0x80000000u) ? (u & 0x7FFFFFFFu) : ~u;
    return __uint_as_float(v);
}
__device__ __forceinline__ float sigmoidf_(float x) { return 1.f / (1.f + expf(-x)); }
__device__ __forceinline__ uint32_t smem_u32(const void* p) {
    uint32_t a;
    asm("{ .reg .u64 t; cvta.to.shared.u64 t, %1; cvt.u32.u64 %0, t; }" : "=r"(a) : "l"(p));
    return a;
}
__device__ __forceinline__ uint32_t ldu(const __half* p) { return *(const uint32_t*)p; }

__device__ __forceinline__ void mma_f16(float4& d, const uint32_t a[4], const uint32_t b[2]) {
    asm volatile(
        "mma.sync.aligned.m16n8k16.row.col.f32.f16.f16.f32 "
        "{%0,%1,%2,%3}, {%4,%5,%6,%7}, {%8,%9}, {%0,%1,%2,%3};\n"
        : "+f"(d.x), "+f"(d.y), "+f"(d.z), "+f"(d.w)
        : "r"(a[0]), "r"(a[1]), "r"(a[2]), "r"(a[3]), "r"(b[0]), "r"(b[1]));
}

// one BK=32 tile step via ldmatrix. A tile: [128][PITCH] half2-words.
// B tile: [N][PITCH]. NT n-subtiles per warp (NT even).
template<int NT>
__device__ __forceinline__ void mma_blk(uint32_t aBase, uint32_t bBase,
                                        float4 (*acc)[NT],
                                        int warp_m, int warp_n, int lane)
{
    const int rowA = warp_m * 32 + (lane & 15);
    const int hiA  = (lane >> 4) & 1;
    const int nB   = warp_n * (NT * 8) + (lane & 7) + ((lane & 16) ? 8 : 0);
    const int hB   = (lane & 8) ? 4 : 0;
#pragma unroll
    for (int ks = 0; ks < 2; ks++) {
        uint32_t a[2][4];
#pragma unroll
        for (int mt = 0; mt < 2; mt++) {
            uint32_t ad = aBase + (uint32_t)(((rowA + mt * 16) * PITCH + hiA * 4 + ks * 8) << 2);
            asm volatile("ldmatrix.sync.aligned.m8n8.x4.shared.b16 {%0,%1,%2,%3}, [%4];"
                : "=r"(a[mt][0]), "=r"(a[mt][1]), "=r"(a[mt][2]), "=r"(a[mt][3]) : "r"(ad));
        }
        uint32_t b[NT][2];
#pragma unroll
        for (int p = 0; p < NT / 2; p++) {
            uint32_t bd = bBase + (uint32_t)(((nB + p * 16) * PITCH + hB + ks * 8) << 2);
            asm volatile("ldmatrix.sync.aligned.m8n8.x4.shared.b16 {%0,%1,%2,%3}, [%4];"
                : "=r"(b[2 * p][0]), "=r"(b[2 * p][1]),
                  "=r"(b[2 * p + 1][0]), "=r"(b[2 * p + 1][1]) : "r"(bd));
        }
#pragma unroll
        for (int mt = 0; mt < 2; mt++)
#pragma unroll
            for (int nt = 0; nt < NT; nt++) mma_f16(acc[mt][nt], a[mt], b[nt]);
    }
}

// ---------------- prep kernels ------------------------------------------------
__global__ void k_prep_inputs(const float* __restrict__ memory, const float* __restrict__ msg) {
    int i = blockIdx.x * blockDim.x + threadIdx.x;
    const int NM = N_NODES * 128;
    if (i < NM) g_mem_h[i] = __float2half_rn(memory[i]);
    else if (i < NM + N_EVENTS * 64) g_msg_h[i - NM] = __float2half_rn(msg[i - NM]);
}
__global__ void k_prepw(const float* __restrict__ Wih, const float* __restrict__ Whh,
                        const float* __restrict__ Wk, const float* __restrict__ Wv,
                        const float* __restrict__ We, const float* __restrict__ Wq,
                        const float* __restrict__ Wskip,
                        const float* __restrict__ Wls, const float* __restrict__ Wld) {
    int i = blockIdx.x * blockDim.x + threadIdx.x;
    if (i < 512 * 384) {                         // W_comb
        int rg = i / 384, k = i % 384;
        int g = rg >> 7, r = rg & 127;
        float v;
        if (g < 2) {
            v = Wih[(size_t)(g * 128 + r) * 384 + k];
            if (k < 128) v += Whh[(size_t)(g * 128 + r) * 128 + k];
        } else if (g == 2) v = Wih[(size_t)(256 + r) * 384 + k];
        else               v = (k < 128) ? Whh[(size_t)(256 + r) * 128 + k] : 0.f;
        g_wcomb[i] = __float2half_rn(v);
        return;
    }
    i -= 512 * 384;
    if (i < 256 * 256) {                         // Wkv
        int o = i / 256, k = i % 256;
        float v;
        if (o < 128) v = (k < 128) ? Wk[(size_t)o * 128 + k] : We[(size_t)o * 128 + (k - 128)];
        else { int o2 = o - 128;
               v = (k < 128) ? Wv[(size_t)o2 * 128 + k] : We[(size_t)o2 * 128 + (k - 128)]; }
        g_wkv[i] = __float2half_rn(v);
        return;
    }
    i -= 256 * 256;
    if (i < 128 * 128) { g_wq[i] = __float2half_rn(Wq[i]); return; }
    i -= 128 * 128;
    if (i < 128 * 128) { g_wskip[i] = __float2half_rn(Wskip[i]); return; }
    i -= 128 * 128;
    if (i < 128 * 256) {                         // Wl hi/lo
        int n = i / 256, k = i % 256;
        float v = (k < 128) ? Wls[(size_t)n * 128 + k] : Wld[(size_t)n * 128 + (k - 128)];
        __half hh = __float2half_rn(v);
        g_wl[i] = hh;
        g_wl_lo[i] = __float2half_rn(v - __half2float(hh));
    }
}

// ---------------- small kernels ----------------------------------------------
__global__ void k_init() {
    int i = blockIdx.x * blockDim.x + threadIdx.x;
    if (i < N_NODES) g_last_pos[i] = -1;
    if (i < 2 * N_NODES) { g_mx[i] = 0u; g_denom[i] = 0.f; }
    if (i == 0) g_count = 0;
}
__global__ void k_lastpos(const int* __restrict__ src, const int* __restrict__ dst) {
    int j = blockIdx.x * blockDim.x + threadIdx.x;
    if (j >= TWO_E) return;
    int id = (j < N_EVENTS) ? src[j] : dst[j - N_EVENTS];
    atomicMax(&g_last_pos[id], j);
}
__global__ void k_compact(const int* __restrict__ src, const int* __restrict__ dst,
                          const float* __restrict__ lu, const float* __restrict__ t) {
    int j = blockIdx.x * blockDim.x + threadIdx.x;
    if (j >= TWO_E) return;
    int e = (j < N_EVENTS) ? j : j - N_EVENTS;
    int id = (j < N_EVENTS) ? src[e] : dst[e];
    if (g_last_pos[id] == j) {
        int p = atomicAdd(&g_count, 1);
        g_sel[p] = j;
        g_lu_new[id] = fmaxf(lu[id], t[e]);
    }
}
__global__ void k_te_gru(const float* __restrict__ last_update, const float* __restrict__ t,
                         const int* __restrict__ src, const int* __restrict__ dst,
                         const float* __restrict__ time_w, const float* __restrict__ time_b)
{
    int i = blockIdx.x * blockDim.x + threadIdx.x;
    int m = i >> 6, j = i & 63;
    if (m >= g_count) return;
    int sel = g_sel[m];
    int e  = (sel < N_EVENTS) ? sel : sel - N_EVENTS;
    int id = (sel < N_EVENTS) ? src[e] : dst[e];
    float dt = t[e] - last_update[id];
    g_te_h[(size_t)m * 64 + j] = __float2half_rn(cosf(fmaf(dt, time_w[j], time_b[j])));
}
__global__ void k_te_edge(const float* __restrict__ t, const int* __restrict__ src,
                          const float* __restrict__ time_w, const float* __restrict__ time_b)
{
    int i = blockIdx.x * blockDim.x + threadIdx.x;
    if (i >= N_EVENTS * 64) return;
    int e = i >> 6, j = i & 63;
    float rt = g_lu_new[src[e]] - t[e];
    g_te2_h[i] = __float2half_rn(cosf(fmaf(rt, time_w[j], time_b[j])));
}
__global__ void k_expsum(const int* __restrict__ dst) {
    int i = blockIdx.x * blockDim.x + threadIdx.x;
    if (i >= N_EVENTS * 2) return;
    int e = i >> 1, h = i & 1;
    int dn = dst[e];
    float a = expf(g_logit[i] - dec_f(g_mx[dn * 2 + h]));
    g_aexp[i] = a;
    atomicAdd(&g_denom[dn * 2 + h], a);
}
__global__ void k_scatter(const int* __restrict__ dst) {
    int e = blockIdx.x, d = threadIdx.x;
    int dn = dst[e], h = d >> 6;
    float attn = g_aexp[e * 2 + h] / g_denom[dn * 2 + h];
    atomicAdd(&g_z[(size_t)dn * 128 + d], attn * g_kv[(size_t)e * 256 + 128 + d]);
}

// ---------------- GRU: K=384 combined-weight fp16 MMA, fused gates ------------
// A = [mem_id(128) | mem_oth(128) | msg(64) | te(64)] ; 12 BK=32 tiles.
// Gates r,z,i_n over all K; h_n only K<128 (zeros elsewhere in W_comb).
__global__ __launch_bounds__(256) void k_gru(
    const float* __restrict__ memory,
    const int* __restrict__ src, const int* __restrict__ dst,
    const float* __restrict__ bih, const float* __restrict__ bhh)
{
    const int count = g_count;
    const int m0 = blockIdx.x * 128;
    if (m0 >= count) return;
    const int q = blockIdx.y;
    const int tid = threadIdx.x, lane = tid & 31, wid = tid >> 5;
    const int warp_m = wid & 3, warp_n = wid >> 2;

    __shared__ int s_id[128], s_oth[128], s_e[128], s_mm[128];
    __shared__ __align__(16) uint32_t As2[128 * PITCH];
    __shared__ __align__(16) uint32_t Bs2[4 * 32 * PITCH];
    const uint32_t aBase = smem_u32(As2);
    const uint32_t bBase = smem_u32(Bs2);

    if (tid < 128) {
        int mm = min(m0 + tid, count - 1);
        int j = g_sel[mm];
        int e = (j < N_EVENTS) ? j : j - N_EVENTS;
        s_id[tid]  = (j < N_EVENTS) ? src[e] : dst[e];
        s_oth[tid] = (j < N_EVENTS) ? dst[e] : src[e];
        s_e[tid] = e; s_mm[tid] = mm;
    }
    __syncthreads();

    float4 acc[4][2][2];
#pragma unroll
    for (int g = 0; g < 4; g++)
#pragma unroll
        for (int i = 0; i < 2; i++)
#pragma unroll
            for (int j = 0; j < 2; j++) acc[g][i][j] = make_float4(0.f, 0.f, 0.f, 0.f);

    for (int tile = 0; tile < 12; tile++) {
        const int k0 = tile * 32;
#pragma unroll
        for (int s = 0; s < 8; s++) {           // A: 128 x 16 uint (pure copies)
            int idx = tid + s * 256;
            int c = idx & 15, m = idx >> 4;
            int k = k0 + 2 * c;
            uint32_t u;
            if (k < 128)      u = ldu(&g_mem_h[(size_t)s_id[m] * 128 + k]);
            else if (k < 256) u = ldu(&g_mem_h[(size_t)s_oth[m] * 128 + (k - 128)]);
            else if (k < 320) u = ldu(&g_msg_h[(size_t)s_e[m] * 64 + (k - 256)]);
            else              u = ldu(&g_te_h[(size_t)s_mm[m] * 64 + (k - 320)]);
            As2[m * PITCH + c] = u;
        }
#pragma unroll
        for (int s = 0; s < 8; s++) {           // B: 4 gates x 32 rows x 16 uint
            int idx = tid + s * 256;
            int slot = idx >> 9;
            int n = (idx >> 4) & 31;
            int c = idx & 15;
            int rg = slot * 128 + q * 32 + n;
            Bs2[slot * (32 * PITCH) + n * PITCH + c] =
                ldu(&g_wcomb[(size_t)rg * 384 + k0 + 2 * c]);
        }
        __syncthreads();
        mma_blk<2>(aBase, bBase,                   acc[0], warp_m, warp_n, lane);
        mma_blk<2>(aBase, bBase + 32 * PITCH * 4,  acc[1], warp_m, warp_n, lane);
        mma_blk<2>(aBase, bBase + 64 * PITCH * 4,  acc[2], warp_m, warp_n, lane);
        if (k0 < 128)
            mma_blk<2>(aBase, bBase + 96 * PITCH * 4, acc[3], warp_m, warp_n, lane);
        __syncthreads();
    }

    // fused gates epilogue (writes fp16 new-memory)
    const int g_ = lane >> 2, t_ = lane & 3;
#pragma unroll
    for (int mt = 0; mt < 2; mt++)
#pragma unroll
    for (int nt = 0; nt < 2; nt++) {
        int cl = warp_n * 16 + nt * 8 + 2 * t_;
        int d = q * 32 + cl;
        float br0 = bih[d] + bhh[d],             br1 = bih[d + 1] + bhh[d + 1];
        float bz0 = bih[128 + d] + bhh[128 + d], bz1 = bih[129 + d] + bhh[129 + d];
        float bi0 = bih[256 + d],                bi1 = bih[257 + d];
        float bn0 = bhh[256 + d],                bn1 = bhh[257 + d];
#pragma unroll
        for (int hf = 0; hf < 2; hf++) {
            int rl = warp_m * 32 + mt * 16 + g_ + hf * 8;
            int m = m0 + rl;
            if (m < count) {
                int id = s_id[rl];
                float2 h = *(const float2*)&memory[(size_t)id * 128 + d];
                float R0, R1, Z0, Z1, I0, I1, H0, H1;
                if (hf == 0) {
                    R0 = acc[0][mt][nt].x; R1 = acc[0][mt][nt].y;
                    Z0 = acc[1][mt][nt].x; Z1 = acc[1][mt][nt].y;
                    I0 = acc[2][mt][nt].x; I1 = acc[2][mt][nt].y;
                    H0 = acc[3][mt][nt].x; H1 = acc[3][mt][nt].y;
                } else {
                    R0 = acc[0][mt][nt].z; R1 = acc[0][mt][nt].w;
                    Z0 = acc[1][mt][nt].z; Z1 = acc[1][mt][nt].w;
                    I0 = acc[2][mt][nt].z; I1 = acc[2][mt][nt].w;
                    H0 = acc[3][mt][nt].z; H1 = acc[3][mt][nt].w;
                }
                float r0 = sigmoidf_(R0 + br0), z0 = sigmoidf_(Z0 + bz0);
                float n0 = tanhf(I0 + bi0 + r0 * (H0 + bn0));
                float r1 = sigmoidf_(R1 + br1), z1 = sigmoidf_(Z1 + bz1);
                float n1 = tanhf(I1 + bi1 + r1 * (H1 + bn1));
                __half2 o = __floats2half2_rn((1.f - z0) * n0 + z0 * h.x,
                                              (1.f - z1) * n1 + z1 * h.y);
                *(__half2*)&g_memnew_h[(size_t)id * 128 + d] = o;
            }
        }
    }
}

// ---------------- kv GEMM: [E x 256], fp16, grid=(E/128, 2) -------------------
__global__ __launch_bounds__(256) void k_kv(
    const int* __restrict__ src,
    const float* __restrict__ bk, const float* __restrict__ bv)
{
    const int m0 = blockIdx.x * 128;
    const int bn0 = blockIdx.y * 128;
    const int tid = threadIdx.x, lane = tid & 31, wid = tid >> 5;
    const int warp_m = wid & 3, warp_n = wid >> 2, g_ = lane >> 2, t_ = lane & 3;

    __shared__ int s_src[128], s_ec[128];
    __shared__ __align__(16) uint32_t As2[128 * PITCH];
    __shared__ __align__(16) uint32_t Bs2[128 * PITCH];
    const uint32_t aBase = smem_u32(As2);
    const uint32_t bBase = smem_u32(Bs2);

    if (tid < 128) {
        int e = min(m0 + tid, N_EVENTS - 1);
        s_src[tid] = src[e]; s_ec[tid] = e;
    }
    __syncthreads();

    float4 acc[2][8];
#pragma unroll
    for (int i = 0; i < 2; i++)
#pragma unroll
        for (int j = 0; j < 8; j++) acc[i][j] = make_float4(0.f, 0.f, 0.f, 0.f);

    for (int tile = 0; tile < 8; tile++) {
        const int k0 = tile * 32;
#pragma unroll
        for (int s = 0; s < 8; s++) {
            int idx = tid + s * 256;
            int c = idx & 15, m = idx >> 4;
            int k = k0 + 2 * c;
            uint32_t u;
            if (k < 128)      u = ldu(&g_memnew_h[(size_t)s_src[m] * 128 + k]);
            else if (k < 192) u = ldu(&g_te2_h[(size_t)s_ec[m] * 64 + (k - 128)]);
            else              u = ldu(&g_msg_h[(size_t)s_ec[m] * 64 + (k - 192)]);
            As2[m * PITCH + c] = u;
        }
#pragma unroll
        for (int s = 0; s < 8; s++) {
            int idx = tid + s * 256;
            int c = idx & 15, n = idx >> 4;
            Bs2[n * PITCH + c] = ldu(&g_wkv[(size_t)(bn0 + n) * 256 + k0 + 2 * c]);
        }
        __syncthreads();
        mma_blk<8>(aBase, bBase, acc, warp_m, warp_n, lane);
        __syncthreads();
    }
#pragma unroll
    for (int mt = 0; mt < 2; mt++)
#pragma unroll
        for (int nt = 0; nt < 8; nt++) {
            int r0 = m0 + warp_m * 32 + mt * 16 + g_;
            int c  = bn0 + warp_n * 64 + nt * 8 + 2 * t_;
            float b0 = (c < 128) ? bk[c] : bv[c - 128];
            float b1 = (c + 1 < 128) ? bk[c + 1] : bv[c + 1 - 128];
            if (r0 < N_EVENTS)
                *(float2*)&g_kv[(size_t)r0 * 256 + c] =
                    make_float2(acc[mt][nt].x + b0, acc[mt][nt].y + b1);
            if (r0 + 8 < N_EVENTS)
                *(float2*)&g_kv[(size_t)(r0 + 8) * 256 + c] =
                    make_float2(acc[mt][nt].z + b0, acc[mt][nt].w + b1);
        }
}

// ---------------- q GEMM + fused logit + segment max --------------------------
__global__ __launch_bounds__(256) void k_q(
    const int* __restrict__ dst, const float* __restrict__ bq)
{
    const int m0 = blockIdx.x * 128;
    const int tid = threadIdx.x, lane = tid & 31, wid = tid >> 5;
    const int warp_m = wid & 3, warp_n = wid >> 2, g_ = lane >> 2, t_ = lane & 3;

    __shared__ int s_dst[128];
    __shared__ __align__(16) uint32_t As2[128 * PITCH];
    __shared__ __align__(16) uint32_t Bs2[128 * PITCH];
    __shared__ float logit_s[256];
    const uint32_t aBase = smem_u32(As2);
    const uint32_t bBase = smem_u32(Bs2);

    if (tid < 128) s_dst[tid] = dst[min(m0 + tid, N_EVENTS - 1)];
    logit_s[tid] = 0.f;
    __syncthreads();

    float4 acc[2][8];
#pragma unroll
    for (int i = 0; i < 2; i++)
#pragma unroll
        for (int j = 0; j < 8; j++) acc[i][j] = make_float4(0.f, 0.f, 0.f, 0.f);

    for (int tile = 0; tile < 4; tile++) {
        const int k0 = tile * 32;
#pragma unroll
        for (int s = 0; s < 8; s++) {
            int idx = tid + s * 256;
            int c = idx & 15, m = idx >> 4;
            As2[m * PITCH + c] = ldu(&g_memnew_h[(size_t)s_dst[m] * 128 + k0 + 2 * c]);
        }
#pragma unroll
        for (int s = 0; s < 8; s++) {
            int idx = tid + s * 256;
            int c = idx & 15, n = idx >> 4;
            Bs2[n * PITCH + c] = ldu(&g_wq[(size_t)n * 128 + k0 + 2 * c]);
        }
        __syncthreads();
        mma_blk<8>(aBase, bBase, acc, warp_m, warp_n, lane);
        __syncthreads();
    }
    float p[4] = {0.f, 0.f, 0.f, 0.f};
#pragma unroll
    for (int mt = 0; mt < 2; mt++) {
        int r0 = m0 + warp_m * 32 + mt * 16 + g_;
        int r0c = min(r0, N_EVENTS - 1);
        int r1c = min(r0 + 8, N_EVENTS - 1);
#pragma unroll
        for (int nt = 0; nt < 8; nt++) {
            int c = warp_n * 64 + nt * 8 + 2 * t_;
            float bq0 = bq[c], bq1 = bq[c + 1];
            p[mt * 2 + 0] += (acc[mt][nt].x + bq0) * g_kv[(size_t)r0c * 256 + c]
                           + (acc[mt][nt].y + bq1) * g_kv[(size_t)r0c * 256 + c + 1];
            p[mt * 2 + 1] += (acc[mt][nt].z + bq0) * g_kv[(size_t)r1c * 256 + c]
                           + (acc[mt][nt].w + bq1) * g_kv[(size_t)r1c * 256 + c + 1];
        }
    }
#pragma unroll
    for (int mt = 0; mt < 2; mt++) {
        int rl = warp_m * 32 + mt * 16 + g_;
        atomicAdd(&logit_s[rl * 2 + warp_n], p[mt * 2 + 0]);
        atomicAdd(&logit_s[(rl + 8) * 2 + warp_n], p[mt * 2 + 1]);
    }
    __syncthreads();
    {
        int rl = tid >> 1, h = tid & 1;
        int m = m0 + rl;
        if (m < N_EVENTS) {
            float lg = logit_s[tid] * 0.125f;
            g_logit[m * 2 + h] = lg;
            atomicMax(&g_mx[(size_t)s_dst[rl] * 2 + h], enc_f(lg));
        }
    }
}

// ---------------- skip GEMM over compacted nodes ------------------------------
__global__ __launch_bounds__(256) void k_skip(
    const int* __restrict__ src, const int* __restrict__ dst,
    const float* __restrict__ bskip)
{
    const int count = g_count;
    const int m0 = blockIdx.x * 128;
    if (m0 >= count) return;
    const int tid = threadIdx.x, lane = tid & 31, wid = tid >> 5;
    const int warp_m = wid & 3, warp_n = wid >> 2, g_ = lane >> 2, t_ = lane & 3;

    __shared__ int s_id[128];
    __shared__ __align__(16) uint32_t As2[128 * PITCH];
    __shared__ __align__(16) uint32_t Bs2[128 * PITCH];
    const uint32_t aBase = smem_u32(As2);
    const uint32_t bBase = smem_u32(Bs2);

    if (tid < 128) {
        int mm = min(m0 + tid, count - 1);
        int j = g_sel[mm];
        int e = (j < N_EVENTS) ? j : j - N_EVENTS;
        s_id[tid] = (j < N_EVENTS) ? src[e] : dst[e];
    }
    __syncthreads();

    float4 acc[2][8];
#pragma unroll
    for (int i = 0; i < 2; i++)
#pragma unroll
        for (int j = 0; j < 8; j++) acc[i][j] = make_float4(0.f, 0.f, 0.f, 0.f);

    for (int tile = 0; tile < 4; tile++) {
        const int k0 = tile * 32;
#pragma unroll
        for (int s = 0; s < 8; s++) {
            int idx = tid + s * 256;
            int c = idx & 15, m = idx >> 4;
            As2[m * PITCH + c] = ldu(&g_memnew_h[(size_t)s_id[m] * 128 + k0 + 2 * c]);
        }
#pragma unroll
        for (int s = 0; s < 8; s++) {
            int idx = tid + s * 256;
            int c = idx & 15, n = idx >> 4;
            Bs2[n * PITCH + c] = ldu(&g_wskip[(size_t)n * 128 + k0 + 2 * c]);
        }
        __syncthreads();
        mma_blk<8>(aBase, bBase, acc, warp_m, warp_n, lane);
        __syncthreads();
    }
#pragma unroll
    for (int mt = 0; mt < 2; mt++)
#pragma unroll
        for (int nt = 0; nt < 8; nt++) {
            int rl = warp_m * 32 + mt * 16 + g_;
            int c  = warp_n * 64 + nt * 8 + 2 * t_;
            float b0 = bskip[c], b1 = bskip[c + 1];
            if (m0 + rl < count) {
                int id = s_id[rl];
                *(float2*)&g_z[(size_t)id * 128 + c] =
                    make_float2(acc[mt][nt].x + b0, acc[mt][nt].y + b1);
            }
            if (m0 + rl + 8 < count) {
                int id = s_id[rl + 8];
                *(float2*)&g_z[(size_t)id * 128 + c] =
                    make_float2(acc[mt][nt].z + b0, acc[mt][nt].w + b1);
            }
        }
}

// ---------------- link predictor: 3x fp16 compensated -------------------------
__global__ __launch_bounds__(256) void k_linkpred(
    const int* __restrict__ src, const int* __restrict__ dst,
    const float* __restrict__ bls, const float* __restrict__ bld,
    const float* __restrict__ Wlf, const float* __restrict__ blf,
    float* __restrict__ out)
{
    const int m0 = blockIdx.x * 128;
    const int tid = threadIdx.x, lane = tid & 31, wid = tid >> 5;
    const int warp_m = wid & 3, warp_n = wid >> 2, g_ = lane >> 2, t_ = lane & 3;

    __shared__ int s_src[128], s_dst[128];
    __shared__ __align__(16) uint32_t Ah2[128 * PITCH];
    __shared__ __align__(16) uint32_t Al2[128 * PITCH];
    __shared__ __align__(16) uint32_t Bh2[128 * PITCH];
    __shared__ __align__(16) uint32_t Bl2[128 * PITCH];
    __shared__ float out_s[128];
    const uint32_t ahB = smem_u32(Ah2), alB = smem_u32(Al2);
    const uint32_t bhB = smem_u32(Bh2), blB = smem_u32(Bl2);

    if (tid < 128) {
        int e = min(m0 + tid, N_EVENTS - 1);
        s_src[tid] = src[e]; s_dst[tid] = dst[e];
        out_s[tid] = 0.f;
    }
    __syncthreads();

    float4 acc[2][8];
#pragma unroll
    for (int i = 0; i < 2; i++)
#pragma unroll
        for (int j = 0; j < 8; j++) acc[i][j] = make_float4(0.f, 0.f, 0.f, 0.f);

    for (int tile = 0; tile < 8; tile++) {
        const int k0 = tile * 32;
#pragma unroll
        for (int s = 0; s < 8; s++) {
            int idx = tid + s * 256;
            int c = idx & 15, m = idx >> 4;
            int k = k0 + 2 * c;
            float2 v = (k < 128) ? *(const float2*)&g_z[(size_t)s_src[m] * 128 + k]
                                 : *(const float2*)&g_z[(size_t)s_dst[m] * 128 + (k - 128)];
            __half2 hh = __floats2half2_rn(v.x, v.y);
            Ah2[m * PITCH + c] = *(uint32_t*)&hh;
            __half2 ll = __floats2half2_rn(v.x - __half2float(__low2half(hh)),
                                           v.y - __half2float(__high2half(hh)));
            Al2[m * PITCH + c] = *(uint32_t*)&ll;
        }
#pragma unroll
        for (int s = 0; s < 8; s++) {
            int idx = tid + s * 256;
            int c = idx & 15, n = idx >> 4;
            Bh2[n * PITCH + c] = ldu(&g_wl[(size_t)n * 256 + k0 + 2 * c]);
            Bl2[n * PITCH + c] = ldu(&g_wl_lo[(size_t)n * 256 + k0 + 2 * c]);
        }
        __syncthreads();
        mma_blk<8>(ahB, bhB, acc, warp_m, warp_n, lane);
        mma_blk<8>(ahB, blB, acc, warp_m, warp_n, lane);
        mma_blk<8>(alB, bhB, acc, warp_m, warp_n, lane);
        __syncthreads();
    }
    float p[4] = {0.f, 0.f, 0.f, 0.f};
#pragma unroll
    for (int mt = 0; mt < 2; mt++) {
#pragma unroll
        for (int nt = 0; nt < 8; nt++) {
            int c = warp_n * 64 + nt * 8 + 2 * t_;
            float bb0 = bls[c] + bld[c], bb1 = bls[c + 1] + bld[c + 1];
            float w0 = Wlf[c], w1 = Wlf[c + 1];
            p[mt * 2 + 0] += fmaxf(acc[mt][nt].x + bb0, 0.f) * w0
                           + fmaxf(acc[mt][nt].y + bb1, 0.f) * w1;
            p[mt * 2 + 1] += fmaxf(acc[mt][nt].z + bb0, 0.f) * w0
                           + fmaxf(acc[mt][nt].w + bb1, 0.f) * w1;
        }
    }
#pragma unroll
    for (int mt = 0; mt < 2; mt++) {
        int rl = warp_m * 32 + mt * 16 + g_;
        atomicAdd(&out_s[rl], p[mt * 2 + 0]);
        atomicAdd(&out_s[rl + 8], p[mt * 2 + 1]);
    }
    __syncthreads();
    if (tid < 128 && m0 + tid < N_EVENTS)
        out[m0 + tid] = out_s[tid] + blf[0];
}

// ---------------- launch -------------------------------------------------------
extern "C" void kernel_launch(void* const* d_in, const int* in_sizes, int n_in,
                              void* d_out, int out_size)
{
    const float* memory      = (const float*)d_in[0];
    const float* last_update = (const float*)d_in[1];
    const float* t           = (const float*)d_in[2];
    const float* msg         = (const float*)d_in[3];
    const int*   src         = (const int*)d_in[4];
    const int*   dst         = (const int*)d_in[5];
    const float* time_w      = (const float*)d_in[6];
    const float* time_b      = (const float*)d_in[7];
    const float* gru_Wih     = (const float*)d_in[8];
    const float* gru_bih     = (const float*)d_in[9];
    const float* gru_Whh     = (const float*)d_in[10];
    const float* gru_bhh     = (const float*)d_in[11];
    const float* Wq          = (const float*)d_in[12];
    const float* bq          = (const float*)d_in[13];
    const float* Wk          = (const float*)d_in[14];
    const float* bk          = (const float*)d_in[15];
    const float* Wv          = (const float*)d_in[16];
    const float* bv          = (const float*)d_in[17];
    const float* We          = (const float*)d_in[18];
    const float* Wskip       = (const float*)d_in[19];
    const float* bskip       = (const float*)d_in[20];
    const float* Wls         = (const float*)d_in[21];
    const float* bls         = (const float*)d_in[22];
    const float* Wld         = (const float*)d_in[23];
    const float* bld         = (const float*)d_in[24];
    const float* Wlf         = (const float*)d_in[25];
    const float* blf         = (const float*)d_in[26];
    float* out = (float*)d_out;

    const int PREPW_N = 512 * 384 + 256 * 256 + 128 * 128 + 128 * 128 + 128 * 256;
    const int PREPI_N = N_NODES * 128 + N_EVENTS * 64;

    k_init<<<(2 * N_NODES + 255) / 256, 256>>>();
    k_prepw<<<(PREPW_N + 255) / 256, 256>>>(gru_Wih, gru_Whh, Wk, Wv, We, Wq, Wskip, Wls, Wld);
    k_prep_inputs<<<(PREPI_N + 255) / 256, 256>>>(memory, msg);
    k_lastpos<<<(TWO_E + 255) / 256, 256>>>(src, dst);
    k_compact<<<(TWO_E + 255) / 256, 256>>>(src, dst, last_update, t);
    k_te_gru<<<(TWO_E * 64 + 255) / 256, 256>>>(last_update, t, src, dst, time_w, time_b);
    k_te_edge<<<(N_EVENTS * 64 + 255) / 256, 256>>>(t, src, time_w, time_b);
    {
        dim3 grid((TWO_E + 127) / 128, 4);
        k_gru<<<grid, 256>>>(memory, src, dst, gru_bih, gru_bhh);
    }
    {
        dim3 grid((N_EVENTS + 127) / 128, 2);
        k_kv<<<grid, 256>>>(src, bk, bv);
    }
    k_q<<<(N_EVENTS + 127) / 128, 256>>>(dst, bq);
    k_expsum<<<(N_EVENTS * 2 + 255) / 256, 256>>>(dst);
    k_skip<<<(TWO_E + 127) / 128, 256>>>(src, dst, bskip);
    k_scatter<<<N_EVENTS, 128>>>(dst);
    k_linkpred<<<(N_EVENTS + 127) / 128, 256>>>(src, dst, bls, bld, Wlf, blf, out);
}